// round 1
// baseline (speedup 1.0000x reference)
#include <cuda_runtime.h>
#include <math.h>

#define Bb    2
#define Tt    4096
#define DM    2048
#define NH    32
#define NKV   8
#define DH    64
#define GRP   4
#define SS    1028      // SINK + WINDOW
#define SINKN 4
#define POS_SHIFT 3068  // Tt - WINDOW - SINK

// ---------------- scratch (static device globals; no allocations) -------------
__device__ float g_xs  [(size_t)Bb*SS*DM];          // gathered sliced x rows
__device__ float g_qtmp[(size_t)Bb*Tt*DM];          // x @ wq^T
__device__ float g_ktmp[(size_t)Bb*SS*(NKV*DH)];    // xs @ wk^T
__device__ float g_vtmp[(size_t)Bb*SS*(NKV*DH)];    // xs @ wv^T
__device__ float g_Qh  [(size_t)Bb*NH *Tt*DH];      // [b][h][t][d], roped
__device__ float g_Kh  [(size_t)Bb*NKV*SS*DH];      // [b][kvh][s][d], roped
__device__ float g_Vh  [(size_t)Bb*NKV*SS*DH];      // [b][kvh][s][d]
__device__ float g_sc  [(size_t)Bb*NH*Tt*SS];       // scores / probs (1.08 GB)
__device__ float g_ctx [(size_t)Bb*Tt*DM];          // attention output, [b][t][h*d]

// ---------------- generic SGEMM: C[M,N] = A[M,K] * B[N,K]^T -------------------
// 128x128 block tile, BK=8, 8x8 per thread, 256 threads.
__device__ __forceinline__ void sgemm_abt_dev(const float* __restrict__ A,
                                              const float* __restrict__ Bw,
                                              float* __restrict__ C,
                                              int M, int N, int K) {
    const int BM = 128, BN = 128, BK = 8, TM = 8, TN = 8;
    __shared__ float As[BK][BM];
    __shared__ float Bs[BK][BN];
    int tid = threadIdx.x;
    int tr = tid >> 4, tc = tid & 15;
    int aRow = tid >> 1;
    int aCol = (tid & 1) * 4;
    float acc[TM][TN];
    #pragma unroll
    for (int i = 0; i < TM; i++)
        #pragma unroll
        for (int j = 0; j < TN; j++) acc[i][j] = 0.f;

    for (int k0 = 0; k0 < K; k0 += BK) {
        int gm = blockIdx.y * BM + aRow;
        #pragma unroll
        for (int i = 0; i < 4; i++) {
            int gk = k0 + aCol + i;
            As[aCol + i][aRow] = (gm < M) ? A[(size_t)gm * K + gk] : 0.f;
        }
        int gn = blockIdx.x * BN + aRow;
        #pragma unroll
        for (int i = 0; i < 4; i++) {
            int gk = k0 + aCol + i;
            Bs[aCol + i][aRow] = (gn < N) ? Bw[(size_t)gn * K + gk] : 0.f;
        }
        __syncthreads();
        #pragma unroll
        for (int kk = 0; kk < BK; kk++) {
            float a[TM], b[TN];
            #pragma unroll
            for (int i = 0; i < TM; i++) a[i] = As[kk][tr * TM + i];
            #pragma unroll
            for (int j = 0; j < TN; j++) b[j] = Bs[kk][tc * TN + j];
            #pragma unroll
            for (int i = 0; i < TM; i++)
                #pragma unroll
                for (int j = 0; j < TN; j++) acc[i][j] += a[i] * b[j];
        }
        __syncthreads();
    }
    #pragma unroll
    for (int i = 0; i < TM; i++) {
        int row = blockIdx.y * BM + tr * TM + i;
        if (row >= M) continue;
        #pragma unroll
        for (int j = 0; j < TN; j++) {
            int col = blockIdx.x * BN + tc * TN + j;
            if (col < N) C[(size_t)row * N + col] = acc[i][j];
        }
    }
}

// ---------------- wrappers (scratch referenced as globals) --------------------
__global__ void k_gemm_q(const float* __restrict__ x, const float* __restrict__ wq) {
    sgemm_abt_dev(x, wq, g_qtmp, Bb * Tt, DM, DM);
}
__global__ void k_gemm_k(const float* __restrict__ wk) {
    sgemm_abt_dev(g_xs, wk, g_ktmp, Bb * SS, NKV * DH, DM);
}
__global__ void k_gemm_v(const float* __restrict__ wv) {
    sgemm_abt_dev(g_xs, wv, g_vtmp, Bb * SS, NKV * DH, DM);
}
__global__ void k_proj(const float* __restrict__ wp, float* __restrict__ out) {
    sgemm_abt_dev(g_ctx, wp, out, Bb * Tt, DM, DM);
}

// ---------------- gather sliced rows of x -------------------------------------
__global__ void k_gather(const float* __restrict__ x) {
    size_t idx = (size_t)blockIdx.x * blockDim.x + threadIdx.x;
    int c = idx % DM;
    int j = (idx / DM) % SS;
    int b = idx / ((size_t)DM * SS);
    int pos = (j < SINKN) ? j : j + POS_SHIFT;
    g_xs[idx] = x[((size_t)b * Tt + pos) * DM + c];
}

// ---------------- RoPE (double-precision angles) + layout permute -------------
__global__ void k_rope_q() {
    size_t idx = (size_t)blockIdx.x * blockDim.x + threadIdx.x;
    int i = idx & 31;
    size_t rest = idx >> 5;
    int h = rest % NH; rest /= NH;
    int t = rest % Tt;
    int b = rest / Tt;
    size_t src = ((size_t)b * Tt + t) * DM + h * DH;
    float x1 = g_qtmp[src + i];
    float x2 = g_qtmp[src + i + 32];
    double inv = pow(10000.0, -(double)i / 32.0);
    double ang = (double)t * inv;
    float c = (float)cos(ang), s = (float)sin(ang);
    size_t o = (((size_t)b * NH + h) * Tt + t) * DH;
    g_Qh[o + i]      = x1 * c - x2 * s;
    g_Qh[o + i + 32] = x2 * c + x1 * s;
}

__global__ void k_rope_k() {
    size_t idx = (size_t)blockIdx.x * blockDim.x + threadIdx.x;
    int i = idx & 31;
    size_t rest = idx >> 5;
    int kh = rest % NKV; rest /= NKV;
    int j = rest % SS;
    int b = rest / SS;
    int pos = (j < SINKN) ? j : j + POS_SHIFT;
    size_t src = ((size_t)b * SS + j) * (NKV * DH) + kh * DH;
    float x1 = g_ktmp[src + i];
    float x2 = g_ktmp[src + i + 32];
    double inv = pow(10000.0, -(double)i / 32.0);
    double ang = (double)pos * inv;
    float c = (float)cos(ang), s = (float)sin(ang);
    size_t o = (((size_t)b * NKV + kh) * SS + j) * DH;
    g_Kh[o + i]      = x1 * c - x2 * s;
    g_Kh[o + i + 32] = x2 * c + x1 * s;
}

__global__ void k_perm_v() {
    size_t idx = (size_t)blockIdx.x * blockDim.x + threadIdx.x;
    int d = idx & 63;
    size_t rest = idx >> 6;
    int kh = rest % NKV; rest /= NKV;
    int j = rest % SS;
    int b = rest / SS;
    g_Vh[(((size_t)b * NKV + kh) * SS + j) * DH + d] =
        g_vtmp[((size_t)b * SS + j) * (NKV * DH) + kh * DH + d];
}

// ---------------- scores = Q K^T * 0.125, masked (batched GEMM) ---------------
// grid: x = s-tiles (9), y = t-tiles (32), z = b*H+h (64)
__global__ void k_scores() {
    const int BM = 128, BN = 128, BK = 8, TM = 8, TN = 8;
    int z = blockIdx.z;
    int b = z / NH, h = z % NH, kvh = h / GRP;
    const float* A  = g_Qh + (size_t)z * Tt * DH;
    const float* Bw = g_Kh + ((size_t)b * NKV + kvh) * SS * DH;
    float* C = g_sc + (size_t)z * Tt * SS;

    __shared__ float As[BK][BM];
    __shared__ float Bs[BK][BN];
    int tid = threadIdx.x;
    int tr = tid >> 4, tc = tid & 15;
    int aRow = tid >> 1;
    int aCol = (tid & 1) * 4;
    float acc[TM][TN];
    #pragma unroll
    for (int i = 0; i < TM; i++)
        #pragma unroll
        for (int j = 0; j < TN; j++) acc[i][j] = 0.f;

    for (int k0 = 0; k0 < DH; k0 += BK) {
        int gm = blockIdx.y * BM + aRow;   // always < Tt
        #pragma unroll
        for (int i = 0; i < 4; i++)
            As[aCol + i][aRow] = A[(size_t)gm * DH + k0 + aCol + i];
        int gn = blockIdx.x * BN + aRow;
        #pragma unroll
        for (int i = 0; i < 4; i++)
            Bs[aCol + i][aRow] = (gn < SS) ? Bw[(size_t)gn * DH + k0 + aCol + i] : 0.f;
        __syncthreads();
        #pragma unroll
        for (int kk = 0; kk < BK; kk++) {
            float a[TM], bv[TN];
            #pragma unroll
            for (int i = 0; i < TM; i++) a[i] = As[kk][tr * TM + i];
            #pragma unroll
            for (int j = 0; j < TN; j++) bv[j] = Bs[kk][tc * TN + j];
            #pragma unroll
            for (int i = 0; i < TM; i++)
                #pragma unroll
                for (int j = 0; j < TN; j++) acc[i][j] += a[i] * bv[j];
        }
        __syncthreads();
    }
    #pragma unroll
    for (int i = 0; i < TM; i++) {
        int row = blockIdx.y * BM + tr * TM + i;
        #pragma unroll
        for (int j = 0; j < TN; j++) {
            int col = blockIdx.x * BN + tc * TN + j;
            if (col < SS) {
                float v = acc[i][j] * 0.125f;      // 1/sqrt(64)
                if (col > row) v = -1e30f;          // top-left aligned causal
                C[(size_t)row * SS + col] = v;
            }
        }
    }
}

// ---------------- row softmax over S=1028, in place ---------------------------
__global__ void k_softmax() {
    size_t row = blockIdx.x;
    float* p = g_sc + row * SS;
    int tid = threadIdx.x;
    __shared__ float red[256];
    float m = -1e38f;
    for (int i = tid; i < SS; i += 256) m = fmaxf(m, p[i]);
    red[tid] = m; __syncthreads();
    for (int s = 128; s > 0; s >>= 1) {
        if (tid < s) red[tid] = fmaxf(red[tid], red[tid + s]);
        __syncthreads();
    }
    m = red[0]; __syncthreads();
    float sum = 0.f;
    for (int i = tid; i < SS; i += 256) {
        float e = expf(p[i] - m);
        p[i] = e;
        sum += e;
    }
    red[tid] = sum; __syncthreads();
    for (int s = 128; s > 0; s >>= 1) {
        if (tid < s) red[tid] += red[tid + s];
        __syncthreads();
    }
    float inv = 1.f / red[0];
    for (int i = tid; i < SS; i += 256) p[i] *= inv;
}

// ---------------- ctx = P @ V (batched), write [b][t][h*64+d] ------------------
// grid: x=1, y = t-tiles (64), z = b*H+h (64); 64x64 tile, BK=16, 4x4 per thread
__global__ void k_ctx() {
    const int BM = 64, BK = 16;
    int z = blockIdx.z;
    int b = z / NH, h = z % NH, kvh = h / GRP;
    const float* P = g_sc + (size_t)z * Tt * SS;
    const float* V = g_Vh + ((size_t)b * NKV + kvh) * SS * DH;

    __shared__ float As[BK][BM];
    __shared__ float Bs[BK][DH];
    int tid = threadIdx.x;
    int tr = tid >> 4, tc = tid & 15;
    int ar = tid >> 2, ac = (tid & 3) * 4;
    int br = tid >> 4, bc = (tid & 15) * 4;
    float acc[4][4];
    #pragma unroll
    for (int i = 0; i < 4; i++)
        #pragma unroll
        for (int j = 0; j < 4; j++) acc[i][j] = 0.f;

    for (int k0 = 0; k0 < SS; k0 += BK) {
        int gm = blockIdx.y * BM + ar;
        #pragma unroll
        for (int i = 0; i < 4; i++) {
            int gk = k0 + ac + i;
            As[ac + i][ar] = (gk < SS) ? P[(size_t)gm * SS + gk] : 0.f;
        }
        {
            int gk = k0 + br;
            #pragma unroll
            for (int i = 0; i < 4; i++)
                Bs[br][bc + i] = (gk < SS) ? V[(size_t)gk * DH + bc + i] : 0.f;
        }
        __syncthreads();
        #pragma unroll
        for (int kk = 0; kk < BK; kk++) {
            float a[4], bv[4];
            #pragma unroll
            for (int i = 0; i < 4; i++) a[i] = As[kk][tr * 4 + i];
            #pragma unroll
            for (int j = 0; j < 4; j++) bv[j] = Bs[kk][tc * 4 + j];
            #pragma unroll
            for (int i = 0; i < 4; i++)
                #pragma unroll
                for (int j = 0; j < 4; j++) acc[i][j] += a[i] * bv[j];
        }
        __syncthreads();
    }
    #pragma unroll
    for (int i = 0; i < 4; i++) {
        int t = blockIdx.y * BM + tr * 4 + i;
        #pragma unroll
        for (int j = 0; j < 4; j++) {
            int d = tc * 4 + j;
            g_ctx[((size_t)b * Tt + t) * DM + h * DH + d] = acc[i][j];
        }
    }
}

// ---------------- launch --------------------------------------------------------
extern "C" void kernel_launch(void* const* d_in, const int* in_sizes, int n_in,
                              void* d_out, int out_size) {
    const float* x  = (const float*)d_in[0];
    const float* wq = (const float*)d_in[1];
    const float* wk = (const float*)d_in[2];
    const float* wv = (const float*)d_in[3];
    const float* wp = (const float*)d_in[4];
    float* out = (float*)d_out;

    // gather sliced KV rows of x
    k_gather<<<(Bb * SS * DM) / 256, 256>>>(x);

    // projections
    k_gemm_q<<<dim3(DM / 128, (Bb * Tt) / 128), 256>>>(x, wq);
    k_gemm_k<<<dim3((NKV * DH) / 128, (Bb * SS + 127) / 128), 256>>>(wk);
    k_gemm_v<<<dim3((NKV * DH) / 128, (Bb * SS + 127) / 128), 256>>>(wv);

    // rope + layout
    k_rope_q<<<(Bb * Tt * NH * 32) / 256, 256>>>();
    k_rope_k<<<(Bb * SS * NKV * 32) / 256, 256>>>();
    k_perm_v<<<(Bb * SS * NKV * DH) / 256, 256>>>();

    // attention
    k_scores<<<dim3((SS + 127) / 128, Tt / 128, Bb * NH), 256>>>();
    k_softmax<<<(size_t)Bb * NH * Tt, 256>>>();
    k_ctx<<<dim3(1, Tt / 64, Bb * NH), 256>>>();

    // output projection
    k_proj<<<dim3(DM / 128, (Bb * Tt) / 128), 256>>>(wp, out);
}

// round 2
// speedup vs baseline: 2.1090x; 2.1090x over previous
#include <cuda_runtime.h>
#include <math.h>

#define Bb 2
#define Tt 4096
#define DM 2048
#define NH 32
#define NKV 8
#define DH 64
#define GRP 4
#define SS 1028
#define SINKN 4
#define POS_SHIFT 3068

// ---------------- scratch ------------------------------------------------------
__device__ float g_xs  [(size_t)Bb*SS*DM];
__device__ float g_qtmp[(size_t)Bb*Tt*DM];
__device__ float g_ktmp[(size_t)Bb*SS*(NKV*DH)];
__device__ float g_vtmp[(size_t)Bb*SS*(NKV*DH)];
__device__ float g_Qh  [(size_t)Bb*NH *Tt*DH];
__device__ float g_Kh  [(size_t)Bb*NKV*SS*DH];
__device__ float g_Vh  [(size_t)Bb*NKV*SS*DH];
__device__ float g_ctx [(size_t)Bb*Tt*DM];

// ---------------- tf32 helpers --------------------------------------------------
__device__ __forceinline__ float tf32r(float x) {
    unsigned u; asm("cvt.rna.tf32.f32 %0, %1;" : "=r"(u) : "f"(x));
    return __uint_as_float(u);
}
__device__ __forceinline__ void split2(float v, float &hi, float &lo) {
    hi = tf32r(v);
    lo = tf32r(v - hi);
}
__device__ __forceinline__ void mma8(float c[4], const float a[4], const float b[2]) {
    asm volatile("mma.sync.aligned.m16n8k8.row.col.f32.tf32.tf32.f32 "
        "{%0,%1,%2,%3},{%4,%5,%6,%7},{%8,%9},{%0,%1,%2,%3};"
        : "+f"(c[0]), "+f"(c[1]), "+f"(c[2]), "+f"(c[3])
        : "r"(__float_as_uint(a[0])), "r"(__float_as_uint(a[1])),
          "r"(__float_as_uint(a[2])), "r"(__float_as_uint(a[3])),
          "r"(__float_as_uint(b[0])), "r"(__float_as_uint(b[1])));
}

// ---------------- split-tf32 GEMM: C[M,N] = A[M,K] * W[N,K]^T (fp32-accurate) ----
// 128x128 tile, BK=16, 8 warps (4x2), warp tile 32x64, 3-mma per (hi,lo) pair.
__device__ __forceinline__ void gemm_split_dev(const float* __restrict__ A,
                                               const float* __restrict__ W,
                                               float* __restrict__ C,
                                               int M, int N, int K) {
    __shared__ float Ah[128][20], Al[128][20], Bh[128][20], Bl[128][20];
    int tid = threadIdx.x;
    int lane = tid & 31, wid = tid >> 5;
    int wm = wid >> 1, wn = wid & 1;
    int gp = lane >> 2, q = lane & 3;
    int bm = blockIdx.y * 128, bn = blockIdx.x * 128;

    float acc[2][8][4];
    #pragma unroll
    for (int mt = 0; mt < 2; mt++)
        #pragma unroll
        for (int nt = 0; nt < 8; nt++)
            #pragma unroll
            for (int i = 0; i < 4; i++) acc[mt][nt][i] = 0.f;

    int lrow = tid >> 1;
    int lcol = (tid & 1) * 8;

    for (int k0 = 0; k0 < K; k0 += 16) {
        float4 a0 = {0,0,0,0}, a1 = {0,0,0,0}, b0 = {0,0,0,0}, b1 = {0,0,0,0};
        int arow = bm + lrow;
        if (arow < M) {
            const float* p = A + (size_t)arow * K + k0 + lcol;
            a0 = *(const float4*)p; a1 = *(const float4*)(p + 4);
        }
        int brow = bn + lrow;
        if (brow < N) {
            const float* p = W + (size_t)brow * K + k0 + lcol;
            b0 = *(const float4*)p; b1 = *(const float4*)(p + 4);
        }
        __syncthreads();
        {
            float av[8] = {a0.x,a0.y,a0.z,a0.w,a1.x,a1.y,a1.z,a1.w};
            float bv[8] = {b0.x,b0.y,b0.z,b0.w,b1.x,b1.y,b1.z,b1.w};
            #pragma unroll
            for (int i = 0; i < 8; i++) {
                split2(av[i], Ah[lrow][lcol+i], Al[lrow][lcol+i]);
                split2(bv[i], Bh[lrow][lcol+i], Bl[lrow][lcol+i]);
            }
        }
        __syncthreads();
        #pragma unroll
        for (int kk = 0; kk < 2; kk++) {
            float ah[2][4], al[2][4];
            #pragma unroll
            for (int mt = 0; mt < 2; mt++) {
                int r = wm*32 + mt*16 + gp;
                int c = kk*8 + q;
                ah[mt][0] = Ah[r][c];   ah[mt][1] = Ah[r+8][c];
                ah[mt][2] = Ah[r][c+4]; ah[mt][3] = Ah[r+8][c+4];
                al[mt][0] = Al[r][c];   al[mt][1] = Al[r+8][c];
                al[mt][2] = Al[r][c+4]; al[mt][3] = Al[r+8][c+4];
            }
            #pragma unroll
            for (int nt = 0; nt < 8; nt++) {
                int n = wn*64 + nt*8 + gp;
                int c = kk*8 + q;
                float bh[2] = { Bh[n][c], Bh[n][c+4] };
                float bl[2] = { Bl[n][c], Bl[n][c+4] };
                #pragma unroll
                for (int mt = 0; mt < 2; mt++) {
                    mma8(acc[mt][nt], al[mt], bh);
                    mma8(acc[mt][nt], ah[mt], bl);
                    mma8(acc[mt][nt], ah[mt], bh);
                }
            }
        }
    }
    #pragma unroll
    for (int mt = 0; mt < 2; mt++) {
        int r = bm + wm*32 + mt*16 + gp;
        #pragma unroll
        for (int nt = 0; nt < 8; nt++) {
            int cc = bn + wn*64 + nt*8 + q*2;
            if (r < M) {
                C[(size_t)r * N + cc]     = acc[mt][nt][0];
                C[(size_t)r * N + cc + 1] = acc[mt][nt][1];
            }
            if (r + 8 < M) {
                C[(size_t)(r+8) * N + cc]     = acc[mt][nt][2];
                C[(size_t)(r+8) * N + cc + 1] = acc[mt][nt][3];
            }
        }
    }
}

__global__ void __launch_bounds__(256) k_gemm_q(const float* __restrict__ x, const float* __restrict__ wq) {
    gemm_split_dev(x, wq, g_qtmp, Bb*Tt, DM, DM);
}
__global__ void __launch_bounds__(256) k_gemm_k(const float* __restrict__ wk) {
    gemm_split_dev(g_xs, wk, g_ktmp, Bb*SS, NKV*DH, DM);
}
__global__ void __launch_bounds__(256) k_gemm_v(const float* __restrict__ wv) {
    gemm_split_dev(g_xs, wv, g_vtmp, Bb*SS, NKV*DH, DM);
}
__global__ void __launch_bounds__(256) k_proj(const float* __restrict__ wp, float* __restrict__ out) {
    gemm_split_dev(g_ctx, wp, out, Bb*Tt, DM, DM);
}

// ---------------- gather sliced rows of x --------------------------------------
__global__ void k_gather(const float* __restrict__ x) {
    size_t idx = (size_t)blockIdx.x * blockDim.x + threadIdx.x;
    int c = idx % DM;
    int j = (idx / DM) % SS;
    int b = idx / ((size_t)DM * SS);
    int pos = (j < SINKN) ? j : j + POS_SHIFT;
    g_xs[idx] = x[((size_t)b * Tt + pos) * DM + c];
}

// ---------------- RoPE + layout permute -----------------------------------------
__global__ void k_rope_q() {
    size_t idx = (size_t)blockIdx.x * blockDim.x + threadIdx.x;
    int i = idx & 31;
    size_t rest = idx >> 5;
    int h = rest % NH; rest /= NH;
    int t = rest % Tt;
    int b = rest / Tt;
    size_t src = ((size_t)b * Tt + t) * DM + h * DH;
    float x1 = g_qtmp[src + i];
    float x2 = g_qtmp[src + i + 32];
    double inv = pow(10000.0, -(double)i / 32.0);
    double ang = (double)t * inv;
    float c = (float)cos(ang), s = (float)sin(ang);
    size_t o = (((size_t)b * NH + h) * Tt + t) * DH;
    g_Qh[o + i]      = x1 * c - x2 * s;
    g_Qh[o + i + 32] = x2 * c + x1 * s;
}

__global__ void k_rope_k() {
    size_t idx = (size_t)blockIdx.x * blockDim.x + threadIdx.x;
    int i = idx & 31;
    size_t rest = idx >> 5;
    int kh = rest % NKV; rest /= NKV;
    int j = rest % SS;
    int b = rest / SS;
    int pos = (j < SINKN) ? j : j + POS_SHIFT;
    size_t src = ((size_t)b * SS + j) * (NKV * DH) + kh * DH;
    float x1 = g_ktmp[src + i];
    float x2 = g_ktmp[src + i + 32];
    double inv = pow(10000.0, -(double)i / 32.0);
    double ang = (double)pos * inv;
    float c = (float)cos(ang), s = (float)sin(ang);
    size_t o = (((size_t)b * NKV + kh) * SS + j) * DH;
    g_Kh[o + i]      = x1 * c - x2 * s;
    g_Kh[o + i + 32] = x2 * c + x1 * s;
}

__global__ void k_perm_v() {
    size_t idx = (size_t)blockIdx.x * blockDim.x + threadIdx.x;
    int d = idx & 63;
    size_t rest = idx >> 6;
    int kh = rest % NKV; rest /= NKV;
    int j = rest % SS;
    int b = rest / SS;
    g_Vh[(((size_t)b * NKV + kh) * SS + j) * DH + d] =
        g_vtmp[((size_t)b * SS + j) * (NKV * DH) + kh * DH + d];
}

// ---------------- fused flash attention (tf32 mma, online softmax) --------------
// Block: 256 threads (8 warps), 128 Q rows per block, warp = 16 rows.
// S tiles of 64; skips fully-masked tiles via s_end = min(SS, t0+128).
__global__ void __launch_bounds__(256, 1) k_flash() {
    __shared__ float Ks[64][68];   // (4*gp+q) bank pattern -> conflict free
    __shared__ float Vs[64][72];   // stride 72 (== 8 mod 32) -> conflict free
    int tid = threadIdx.x, lane = tid & 31, wid = tid >> 5;
    int gp = lane >> 2, q = lane & 3;
    int t0 = blockIdx.x * 128;
    int z = blockIdx.y;
    int b = z >> 5, h = z & 31, kvh = h >> 2;
    const float* Qp = g_Qh + (size_t)z * Tt * DH;
    const float* Kp = g_Kh + ((size_t)(b * NKV + kvh)) * SS * DH;
    const float* Vp = g_Vh + ((size_t)(b * NKV + kvh)) * SS * DH;

    int t_r0 = t0 + wid * 16 + gp;
    int t_r1 = t_r0 + 8;
    int warp_tmin = t0 + wid * 16;
    int s_end = min(SS, t0 + 128);

    // Q fragments in registers (tf32), loaded once
    float qa[8][4];
    {
        const float* q0 = Qp + (size_t)t_r0 * DH;
        const float* q1 = Qp + (size_t)t_r1 * DH;
        #pragma unroll
        for (int kk = 0; kk < 8; kk++) {
            qa[kk][0] = tf32r(q0[kk*8 + q]);
            qa[kk][1] = tf32r(q1[kk*8 + q]);
            qa[kk][2] = tf32r(q0[kk*8 + q + 4]);
            qa[kk][3] = tf32r(q1[kk*8 + q + 4]);
        }
    }

    float oacc[8][4];
    #pragma unroll
    for (int nt = 0; nt < 8; nt++)
        #pragma unroll
        for (int i = 0; i < 4; i++) oacc[nt][i] = 0.f;
    float m0 = -1e30f, m1 = -1e30f, l0 = 0.f, l1 = 0.f;

    int src1 = (lane & ~3) | (q >> 1);
    int src2 = src1 + 2;
    bool odd = (q & 1);

    for (int s0 = 0; s0 < s_end; s0 += 64) {
        __syncthreads();
        // load K/V tile (tf32-converted), zero-pad past SS
        #pragma unroll
        for (int i = 0; i < 4; i++) {
            int f = i * 256 + tid;
            int r = f >> 4;
            int c = (f & 15) * 4;
            int srow = s0 + r;
            float4 kv = {0,0,0,0}, vv = {0,0,0,0};
            if (srow < SS) {
                kv = *(const float4*)(Kp + (size_t)srow * DH + c);
                vv = *(const float4*)(Vp + (size_t)srow * DH + c);
            }
            Ks[r][c+0] = tf32r(kv.x); Ks[r][c+1] = tf32r(kv.y);
            Ks[r][c+2] = tf32r(kv.z); Ks[r][c+3] = tf32r(kv.w);
            Vs[r][c+0] = tf32r(vv.x); Vs[r][c+1] = tf32r(vv.y);
            Vs[r][c+2] = tf32r(vv.z); Vs[r][c+3] = tf32r(vv.w);
        }
        __syncthreads();

        // S = Q K^T
        float sacc[8][4];
        #pragma unroll
        for (int nt = 0; nt < 8; nt++)
            #pragma unroll
            for (int i = 0; i < 4; i++) sacc[nt][i] = 0.f;
        #pragma unroll
        for (int kk = 0; kk < 8; kk++) {
            #pragma unroll
            for (int nt = 0; nt < 8; nt++) {
                float bfr[2] = { Ks[nt*8 + gp][kk*8 + q], Ks[nt*8 + gp][kk*8 + q + 4] };
                mma8(sacc[nt], qa[kk], bfr);
            }
        }

        // scale + causal/tail mask
        bool nomask = (s0 + 63 <= warp_tmin) && (s0 + 64 <= SS);
        if (nomask) {
            #pragma unroll
            for (int nt = 0; nt < 8; nt++)
                #pragma unroll
                for (int i = 0; i < 4; i++) sacc[nt][i] *= 0.125f;
        } else {
            #pragma unroll
            for (int nt = 0; nt < 8; nt++) {
                int j = s0 + nt*8 + q*2;
                sacc[nt][0] = (j     <= t_r0 && j     < SS) ? sacc[nt][0]*0.125f : -1e30f;
                sacc[nt][1] = (j + 1 <= t_r0 && j + 1 < SS) ? sacc[nt][1]*0.125f : -1e30f;
                sacc[nt][2] = (j     <= t_r1 && j     < SS) ? sacc[nt][2]*0.125f : -1e30f;
                sacc[nt][3] = (j + 1 <= t_r1 && j + 1 < SS) ? sacc[nt][3]*0.125f : -1e30f;
            }
        }

        // online softmax
        float mx0 = -1e30f, mx1 = -1e30f;
        #pragma unroll
        for (int nt = 0; nt < 8; nt++) {
            mx0 = fmaxf(mx0, fmaxf(sacc[nt][0], sacc[nt][1]));
            mx1 = fmaxf(mx1, fmaxf(sacc[nt][2], sacc[nt][3]));
        }
        mx0 = fmaxf(mx0, __shfl_xor_sync(0xffffffffu, mx0, 1));
        mx0 = fmaxf(mx0, __shfl_xor_sync(0xffffffffu, mx0, 2));
        mx1 = fmaxf(mx1, __shfl_xor_sync(0xffffffffu, mx1, 1));
        mx1 = fmaxf(mx1, __shfl_xor_sync(0xffffffffu, mx1, 2));
        float mn0 = fmaxf(m0, mx0), mn1 = fmaxf(m1, mx1);
        float al0 = __expf(m0 - mn0), al1 = __expf(m1 - mn1);
        float rs0 = 0.f, rs1 = 0.f;
        #pragma unroll
        for (int nt = 0; nt < 8; nt++) {
            float p0 = __expf(sacc[nt][0] - mn0); sacc[nt][0] = p0; rs0 += p0;
            float p1 = __expf(sacc[nt][1] - mn0); sacc[nt][1] = p1; rs0 += p1;
            float p2 = __expf(sacc[nt][2] - mn1); sacc[nt][2] = p2; rs1 += p2;
            float p3 = __expf(sacc[nt][3] - mn1); sacc[nt][3] = p3; rs1 += p3;
        }
        rs0 += __shfl_xor_sync(0xffffffffu, rs0, 1);
        rs0 += __shfl_xor_sync(0xffffffffu, rs0, 2);
        rs1 += __shfl_xor_sync(0xffffffffu, rs1, 1);
        rs1 += __shfl_xor_sync(0xffffffffu, rs1, 2);
        l0 = l0 * al0 + rs0;
        l1 = l1 * al1 + rs1;
        m0 = mn0; m1 = mn1;
        #pragma unroll
        for (int nt = 0; nt < 8; nt++) {
            oacc[nt][0] *= al0; oacc[nt][1] *= al0;
            oacc[nt][2] *= al1; oacc[nt][3] *= al1;
        }

        // O += P @ V  (shuffle C-layout -> A-layout, tf32)
        #pragma unroll
        for (int kt = 0; kt < 8; kt++) {
            float p0 = sacc[kt][0], p1 = sacc[kt][1], p2 = sacc[kt][2], p3 = sacc[kt][3];
            float u0 = __shfl_sync(0xffffffffu, p0, src1);
            float u1 = __shfl_sync(0xffffffffu, p1, src1);
            float v0 = __shfl_sync(0xffffffffu, p0, src2);
            float v1 = __shfl_sync(0xffffffffu, p1, src2);
            float w0 = __shfl_sync(0xffffffffu, p2, src1);
            float w1 = __shfl_sync(0xffffffffu, p3, src1);
            float x0 = __shfl_sync(0xffffffffu, p2, src2);
            float x1 = __shfl_sync(0xffffffffu, p3, src2);
            float pa[4];
            pa[0] = tf32r(odd ? u1 : u0);
            pa[1] = tf32r(odd ? w1 : w0);
            pa[2] = tf32r(odd ? v1 : v0);
            pa[3] = tf32r(odd ? x1 : x0);
            #pragma unroll
            for (int nt = 0; nt < 8; nt++) {
                float bfr[2] = { Vs[kt*8 + q][nt*8 + gp], Vs[kt*8 + q + 4][nt*8 + gp] };
                mma8(oacc[nt], pa, bfr);
            }
        }
    }

    // epilogue: normalize, write [b][t][h*64+d]
    float inv0 = 1.f / l0, inv1 = 1.f / l1;
    float* out0 = g_ctx + ((size_t)b * Tt + t_r0) * DM + h * DH;
    float* out1 = g_ctx + ((size_t)b * Tt + t_r1) * DM + h * DH;
    #pragma unroll
    for (int nt = 0; nt < 8; nt++) {
        int d = nt*8 + q*2;
        out0[d]     = oacc[nt][0] * inv0;
        out0[d + 1] = oacc[nt][1] * inv0;
        out1[d]     = oacc[nt][2] * inv1;
        out1[d + 1] = oacc[nt][3] * inv1;
    }
}

// ---------------- launch ---------------------------------------------------------
extern "C" void kernel_launch(void* const* d_in, const int* in_sizes, int n_in,
                              void* d_out, int out_size) {
    const float* x  = (const float*)d_in[0];
    const float* wq = (const float*)d_in[1];
    const float* wk = (const float*)d_in[2];
    const float* wv = (const float*)d_in[3];
    const float* wp = (const float*)d_in[4];
    float* out = (float*)d_out;

    k_gather<<<(Bb * SS * DM) / 256, 256>>>(x);

    k_gemm_q<<<dim3(DM / 128, (Bb * Tt) / 128), 256>>>(x, wq);
    k_gemm_k<<<dim3((NKV * DH) / 128, (Bb * SS + 127) / 128), 256>>>(wk);
    k_gemm_v<<<dim3((NKV * DH) / 128, (Bb * SS + 127) / 128), 256>>>(wv);

    k_rope_q<<<(Bb * Tt * NH * 32) / 256, 256>>>();
    k_rope_k<<<(Bb * SS * NKV * 32) / 256, 256>>>();
    k_perm_v<<<(Bb * SS * NKV * DH) / 256, 256>>>();

    k_flash<<<dim3(Tt / 128, Bb * NH), 256>>>();

    k_proj<<<dim3(DM / 128, (Bb * Tt) / 128), 256>>>(wp, out);
}

// round 5
// speedup vs baseline: 2.9739x; 1.4101x over previous
#include <cuda_runtime.h>
#include <cuda_bf16.h>
#include <math.h>

#define Bb 2
#define Tt 4096
#define DM 2048
#define NH 32
#define NKV 8
#define DH 64
#define GRP 4
#define SS 1028
#define SINKN 4
#define POS_SHIFT 3068

// ---------------- scratch (all 16B-aligned) --------------------------------------
__device__ __align__(16) __nv_bfloat16 g_xh  [(size_t)Bb*Tt*DM];
__device__ __align__(16) __nv_bfloat16 g_xl  [(size_t)Bb*Tt*DM];
__device__ __align__(16) __nv_bfloat16 g_xsh [(size_t)Bb*SS*DM];
__device__ __align__(16) __nv_bfloat16 g_xsl [(size_t)Bb*SS*DM];
__device__ __align__(16) __nv_bfloat16 g_wqh [(size_t)DM*DM];
__device__ __align__(16) __nv_bfloat16 g_wql [(size_t)DM*DM];
__device__ __align__(16) __nv_bfloat16 g_wkvh[(size_t)1024*DM];
__device__ __align__(16) __nv_bfloat16 g_wkvl[(size_t)1024*DM];
__device__ __align__(16) __nv_bfloat16 g_wph [(size_t)DM*DM];
__device__ __align__(16) __nv_bfloat16 g_wpl [(size_t)DM*DM];
__device__ __align__(16) __nv_bfloat16 g_ctxh[(size_t)Bb*Tt*DM];
__device__ __align__(16) __nv_bfloat16 g_ctxl[(size_t)Bb*Tt*DM];
__device__ __align__(16) float g_qtmp [(size_t)Bb*Tt*DM];
__device__ __align__(16) float g_kvtmp[(size_t)Bb*SS*1024];
__device__ __align__(16) float g_Qh   [(size_t)Bb*NH *Tt*DH];
__device__ __align__(16) float g_Kh   [(size_t)Bb*NKV*SS*DH];
__device__ __align__(16) float g_Vh   [(size_t)Bb*NKV*SS*DH];

// ---------------- helpers ----------------------------------------------------------
__device__ __forceinline__ float tf32r(float x) {
    unsigned u; asm("cvt.rna.tf32.f32 %0, %1;" : "=r"(u) : "f"(x));
    return __uint_as_float(u);
}
__device__ __forceinline__ void mma8(float c[4], const float a[4], const float b[2]) {
    asm volatile("mma.sync.aligned.m16n8k8.row.col.f32.tf32.tf32.f32 "
        "{%0,%1,%2,%3},{%4,%5,%6,%7},{%8,%9},{%0,%1,%2,%3};"
        : "+f"(c[0]), "+f"(c[1]), "+f"(c[2]), "+f"(c[3])
        : "r"(__float_as_uint(a[0])), "r"(__float_as_uint(a[1])),
          "r"(__float_as_uint(a[2])), "r"(__float_as_uint(a[3])),
          "r"(__float_as_uint(b[0])), "r"(__float_as_uint(b[1])));
}
__device__ __forceinline__ void mma16(float c[4], const unsigned a[4], const unsigned b[2]) {
    asm volatile("mma.sync.aligned.m16n8k16.row.col.f32.bf16.bf16.f32 "
        "{%0,%1,%2,%3},{%4,%5,%6,%7},{%8,%9},{%0,%1,%2,%3};"
        : "+f"(c[0]), "+f"(c[1]), "+f"(c[2]), "+f"(c[3])
        : "r"(a[0]), "r"(a[1]), "r"(a[2]), "r"(a[3]), "r"(b[0]), "r"(b[1]));
}
__device__ __forceinline__ void bsplit(float v, __nv_bfloat16& h, __nv_bfloat16& l) {
    h = __float2bfloat16_rn(v);
    l = __float2bfloat16_rn(v - __bfloat162float(h));
}

// ---------------- split kernels (destinations named in DEVICE code) -----------------
__global__ void k_split_x(const float* __restrict__ s) {
    size_t i = (size_t)blockIdx.x * blockDim.x + threadIdx.x;
    bsplit(s[i], g_xh[i], g_xl[i]);
}
__global__ void k_split_wq(const float* __restrict__ s) {
    size_t i = (size_t)blockIdx.x * blockDim.x + threadIdx.x;
    bsplit(s[i], g_wqh[i], g_wql[i]);
}
__global__ void k_split_wk(const float* __restrict__ s) {
    size_t i = (size_t)blockIdx.x * blockDim.x + threadIdx.x;
    bsplit(s[i], g_wkvh[i], g_wkvl[i]);
}
__global__ void k_split_wv(const float* __restrict__ s) {
    size_t i = (size_t)blockIdx.x * blockDim.x + threadIdx.x;
    bsplit(s[i], g_wkvh[(size_t)512*DM + i], g_wkvl[(size_t)512*DM + i]);
}
__global__ void k_split_wp(const float* __restrict__ s) {
    size_t i = (size_t)blockIdx.x * blockDim.x + threadIdx.x;
    bsplit(s[i], g_wph[i], g_wpl[i]);
}
__global__ void k_gatherc(const float* __restrict__ x) {
    size_t idx = (size_t)blockIdx.x * blockDim.x + threadIdx.x;
    int c = idx % DM;
    int j = (idx / DM) % SS;
    int b = idx / ((size_t)DM * SS);
    int pos = (j < SINKN) ? j : j + POS_SHIFT;
    bsplit(x[((size_t)b * Tt + pos) * DM + c], g_xsh[idx], g_xsl[idx]);
}

// ---------------- split-bf16 GEMM: C[M,N] = A[M,K] * W[N,K]^T ------------------------
#define SK  24
#define SKU 12

__device__ __forceinline__ void gemm_bf16_dev(
    const __nv_bfloat16* __restrict__ Ah_, const __nv_bfloat16* __restrict__ Al_,
    const __nv_bfloat16* __restrict__ Wh_, const __nv_bfloat16* __restrict__ Wl_,
    float* __restrict__ C, int M, int N, int K)
{
    __shared__ __align__(16) __nv_bfloat16 sm[4][128 * SK];   // 24 KB
    int tid = threadIdx.x, lane = tid & 31, wid = tid >> 5;
    int wm = wid >> 1, wn = wid & 1, gp = lane >> 2, q = lane & 3;
    int bm = blockIdx.y * 128, bn = blockIdx.x * 128;

    float acc[2][8][4];
    #pragma unroll
    for (int mt = 0; mt < 2; mt++)
        #pragma unroll
        for (int nt = 0; nt < 8; nt++)
            #pragma unroll
            for (int i = 0; i < 4; i++) acc[mt][nt][i] = 0.f;

    int lr = tid >> 1, lc = (tid & 1) * 8;
    int arow = bm + lr; if (arow > M - 1) arow = M - 1;
    int brow = bn + lr; if (brow > N - 1) brow = N - 1;
    const __nv_bfloat16* gsrc[4] = {
        Ah_ + (size_t)arow * K + lc, Al_ + (size_t)arow * K + lc,
        Wh_ + (size_t)brow * K + lc, Wl_ + (size_t)brow * K + lc };
    __nv_bfloat16* sdst[4];
    #pragma unroll
    for (int p = 0; p < 4; p++) sdst[p] = &sm[p][lr * SK + lc];

    int iters = K / 16;
    uint4 stg[4];
    #pragma unroll
    for (int p = 0; p < 4; p++) stg[p] = *(const uint4*)(gsrc[p]);

    for (int i = 0; i < iters; i++) {
        #pragma unroll
        for (int p = 0; p < 4; p++) *(uint4*)(sdst[p]) = stg[p];
        __syncthreads();

        if (i + 1 < iters) {
            int k0 = (i + 1) * 16;
            #pragma unroll
            for (int p = 0; p < 4; p++) stg[p] = *(const uint4*)(gsrc[p] + k0);
        }

        const unsigned* uAh = (const unsigned*)&sm[0][0];
        const unsigned* uAl = (const unsigned*)&sm[1][0];
        const unsigned* uBh = (const unsigned*)&sm[2][0];
        const unsigned* uBl = (const unsigned*)&sm[3][0];

        unsigned ah[2][4], al[2][4];
        #pragma unroll
        for (int mt = 0; mt < 2; mt++) {
            int r = wm * 32 + mt * 16 + gp;
            ah[mt][0] = uAh[r * SKU + q];           al[mt][0] = uAl[r * SKU + q];
            ah[mt][1] = uAh[(r + 8) * SKU + q];     al[mt][1] = uAl[(r + 8) * SKU + q];
            ah[mt][2] = uAh[r * SKU + q + 4];       al[mt][2] = uAl[r * SKU + q + 4];
            ah[mt][3] = uAh[(r + 8) * SKU + q + 4]; al[mt][3] = uAl[(r + 8) * SKU + q + 4];
        }
        #pragma unroll
        for (int nt = 0; nt < 8; nt++) {
            int n = wn * 64 + nt * 8 + gp;
            unsigned bh[2] = { uBh[n * SKU + q], uBh[n * SKU + q + 4] };
            unsigned bl[2] = { uBl[n * SKU + q], uBl[n * SKU + q + 4] };
            #pragma unroll
            for (int mt = 0; mt < 2; mt++) {
                mma16(acc[mt][nt], al[mt], bh);
                mma16(acc[mt][nt], ah[mt], bl);
                mma16(acc[mt][nt], ah[mt], bh);
            }
        }
        __syncthreads();
    }

    #pragma unroll
    for (int mt = 0; mt < 2; mt++) {
        int r = bm + wm * 32 + mt * 16 + gp;
        #pragma unroll
        for (int nt = 0; nt < 8; nt++) {
            int cc = bn + wn * 64 + nt * 8 + q * 2;
            if (r < M) {
                C[(size_t)r * N + cc]     = acc[mt][nt][0];
                C[(size_t)r * N + cc + 1] = acc[mt][nt][1];
            }
            if (r + 8 < M) {
                C[(size_t)(r + 8) * N + cc]     = acc[mt][nt][2];
                C[(size_t)(r + 8) * N + cc + 1] = acc[mt][nt][3];
            }
        }
    }
}

__global__ void __launch_bounds__(256, 2) k_gemm_q() {
    gemm_bf16_dev(g_xh, g_xl, g_wqh, g_wql, g_qtmp, Bb * Tt, DM, DM);
}
__global__ void __launch_bounds__(256, 2) k_gemm_kv() {
    gemm_bf16_dev(g_xsh, g_xsl, g_wkvh, g_wkvl, g_kvtmp, Bb * SS, 1024, DM);
}
__global__ void __launch_bounds__(256, 2) k_proj(float* __restrict__ out) {
    gemm_bf16_dev(g_ctxh, g_ctxl, g_wph, g_wpl, out, Bb * Tt, DM, DM);
}

// ---------------- RoPE + layout permute ----------------------------------------------
__global__ void k_rope_q() {
    size_t idx = (size_t)blockIdx.x * blockDim.x + threadIdx.x;
    int i = idx & 31;
    size_t rest = idx >> 5;
    int h = rest % NH; rest /= NH;
    int t = rest % Tt;
    int b = rest / Tt;
    size_t src = ((size_t)b * Tt + t) * DM + h * DH;
    float x1 = g_qtmp[src + i];
    float x2 = g_qtmp[src + i + 32];
    double inv = pow(10000.0, -(double)i / 32.0);
    double ang = (double)t * inv;
    float c = (float)cos(ang), s = (float)sin(ang);
    size_t o = (((size_t)b * NH + h) * Tt + t) * DH;
    g_Qh[o + i]      = x1 * c - x2 * s;
    g_Qh[o + i + 32] = x2 * c + x1 * s;
}

__global__ void k_rope_k() {
    size_t idx = (size_t)blockIdx.x * blockDim.x + threadIdx.x;
    int i = idx & 31;
    size_t rest = idx >> 5;
    int kh = rest % NKV; rest /= NKV;
    int j = rest % SS;
    int b = rest / SS;
    int pos = (j < SINKN) ? j : j + POS_SHIFT;
    size_t src = ((size_t)b * SS + j) * 1024 + kh * DH;
    float x1 = g_kvtmp[src + i];
    float x2 = g_kvtmp[src + i + 32];
    double inv = pow(10000.0, -(double)i / 32.0);
    double ang = (double)pos * inv;
    float c = (float)cos(ang), s = (float)sin(ang);
    size_t o = (((size_t)b * NKV + kh) * SS + j) * DH;
    g_Kh[o + i]      = x1 * c - x2 * s;
    g_Kh[o + i + 32] = x2 * c + x1 * s;
}

__global__ void k_perm_v() {
    size_t idx = (size_t)blockIdx.x * blockDim.x + threadIdx.x;
    int d = idx & 63;
    size_t rest = idx >> 6;
    int kh = rest % NKV; rest /= NKV;
    int j = rest % SS;
    int b = rest / SS;
    g_Vh[(((size_t)b * NKV + kh) * SS + j) * DH + d] =
        g_kvtmp[((size_t)b * SS + j) * 1024 + 512 + kh * DH + d];
}

// ---------------- fused flash attention (tf32 mma, online softmax) --------------------
__global__ void __launch_bounds__(256, 1) k_flash() {
    __shared__ float Ks[64][68];
    __shared__ float Vs[64][72];
    int tid = threadIdx.x, lane = tid & 31, wid = tid >> 5;
    int gp = lane >> 2, q = lane & 3;
    int t0 = blockIdx.x * 128;
    int z = blockIdx.y;
    int b = z >> 5, h = z & 31, kvh = h >> 2;
    const float* Qp = g_Qh + (size_t)z * Tt * DH;
    const float* Kp = g_Kh + ((size_t)(b * NKV + kvh)) * SS * DH;
    const float* Vp = g_Vh + ((size_t)(b * NKV + kvh)) * SS * DH;

    int t_r0 = t0 + wid * 16 + gp;
    int t_r1 = t_r0 + 8;
    int warp_tmin = t0 + wid * 16;
    int s_end = min(SS, t0 + 128);

    float qa[8][4];
    {
        const float* q0 = Qp + (size_t)t_r0 * DH;
        const float* q1 = Qp + (size_t)t_r1 * DH;
        #pragma unroll
        for (int kk = 0; kk < 8; kk++) {
            qa[kk][0] = tf32r(q0[kk*8 + q]);
            qa[kk][1] = tf32r(q1[kk*8 + q]);
            qa[kk][2] = tf32r(q0[kk*8 + q + 4]);
            qa[kk][3] = tf32r(q1[kk*8 + q + 4]);
        }
    }

    float oacc[8][4];
    #pragma unroll
    for (int nt = 0; nt < 8; nt++)
        #pragma unroll
        for (int i = 0; i < 4; i++) oacc[nt][i] = 0.f;
    float m0 = -1e30f, m1 = -1e30f, l0 = 0.f, l1 = 0.f;

    int src1 = (lane & ~3) | (q >> 1);
    int src2 = src1 + 2;
    bool odd = (q & 1);

    for (int s0 = 0; s0 < s_end; s0 += 64) {
        __syncthreads();
        #pragma unroll
        for (int i = 0; i < 4; i++) {
            int f = i * 256 + tid;
            int r = f >> 4;
            int c = (f & 15) * 4;
            int srow = s0 + r;
            float4 kv = {0,0,0,0}, vv = {0,0,0,0};
            if (srow < SS) {
                kv = *(const float4*)(Kp + (size_t)srow * DH + c);
                vv = *(const float4*)(Vp + (size_t)srow * DH + c);
            }
            Ks[r][c+0] = tf32r(kv.x); Ks[r][c+1] = tf32r(kv.y);
            Ks[r][c+2] = tf32r(kv.z); Ks[r][c+3] = tf32r(kv.w);
            Vs[r][c+0] = tf32r(vv.x); Vs[r][c+1] = tf32r(vv.y);
            Vs[r][c+2] = tf32r(vv.z); Vs[r][c+3] = tf32r(vv.w);
        }
        __syncthreads();

        float sacc[8][4];
        #pragma unroll
        for (int nt = 0; nt < 8; nt++)
            #pragma unroll
            for (int i = 0; i < 4; i++) sacc[nt][i] = 0.f;
        #pragma unroll
        for (int kk = 0; kk < 8; kk++) {
            #pragma unroll
            for (int nt = 0; nt < 8; nt++) {
                float bfr[2] = { Ks[nt*8 + gp][kk*8 + q], Ks[nt*8 + gp][kk*8 + q + 4] };
                mma8(sacc[nt], qa[kk], bfr);
            }
        }

        bool nomask = (s0 + 63 <= warp_tmin) && (s0 + 64 <= SS);
        if (nomask) {
            #pragma unroll
            for (int nt = 0; nt < 8; nt++)
                #pragma unroll
                for (int i = 0; i < 4; i++) sacc[nt][i] *= 0.125f;
        } else {
            #pragma unroll
            for (int nt = 0; nt < 8; nt++) {
                int j = s0 + nt*8 + q*2;
                sacc[nt][0] = (j     <= t_r0 && j     < SS) ? sacc[nt][0]*0.125f : -1e30f;
                sacc[nt][1] = (j + 1 <= t_r0 && j + 1 < SS) ? sacc[nt][1]*0.125f : -1e30f;
                sacc[nt][2] = (j     <= t_r1 && j     < SS) ? sacc[nt][2]*0.125f : -1e30f;
                sacc[nt][3] = (j + 1 <= t_r1 && j + 1 < SS) ? sacc[nt][3]*0.125f : -1e30f;
            }
        }

        float mx0 = -1e30f, mx1 = -1e30f;
        #pragma unroll
        for (int nt = 0; nt < 8; nt++) {
            mx0 = fmaxf(mx0, fmaxf(sacc[nt][0], sacc[nt][1]));
            mx1 = fmaxf(mx1, fmaxf(sacc[nt][2], sacc[nt][3]));
        }
        mx0 = fmaxf(mx0, __shfl_xor_sync(0xffffffffu, mx0, 1));
        mx0 = fmaxf(mx0, __shfl_xor_sync(0xffffffffu, mx0, 2));
        mx1 = fmaxf(mx1, __shfl_xor_sync(0xffffffffu, mx1, 1));
        mx1 = fmaxf(mx1, __shfl_xor_sync(0xffffffffu, mx1, 2));
        float mn0 = fmaxf(m0, mx0), mn1 = fmaxf(m1, mx1);
        float al0 = __expf(m0 - mn0), al1 = __expf(m1 - mn1);
        float rs0 = 0.f, rs1 = 0.f;
        #pragma unroll
        for (int nt = 0; nt < 8; nt++) {
            float p0 = __expf(sacc[nt][0] - mn0); sacc[nt][0] = p0; rs0 += p0;
            float p1 = __expf(sacc[nt][1] - mn0); sacc[nt][1] = p1; rs0 += p1;
            float p2 = __expf(sacc[nt][2] - mn1); sacc[nt][2] = p2; rs1 += p2;
            float p3 = __expf(sacc[nt][3] - mn1); sacc[nt][3] = p3; rs1 += p3;
        }
        rs0 += __shfl_xor_sync(0xffffffffu, rs0, 1);
        rs0 += __shfl_xor_sync(0xffffffffu, rs0, 2);
        rs1 += __shfl_xor_sync(0xffffffffu, rs1, 1);
        rs1 += __shfl_xor_sync(0xffffffffu, rs1, 2);
        l0 = l0 * al0 + rs0;
        l1 = l1 * al1 + rs1;
        m0 = mn0; m1 = mn1;
        #pragma unroll
        for (int nt = 0; nt < 8; nt++) {
            oacc[nt][0] *= al0; oacc[nt][1] *= al0;
            oacc[nt][2] *= al1; oacc[nt][3] *= al1;
        }

        #pragma unroll
        for (int kt = 0; kt < 8; kt++) {
            float p0 = sacc[kt][0], p1 = sacc[kt][1], p2 = sacc[kt][2], p3 = sacc[kt][3];
            float u0 = __shfl_sync(0xffffffffu, p0, src1);
            float u1 = __shfl_sync(0xffffffffu, p1, src1);
            float v0 = __shfl_sync(0xffffffffu, p0, src2);
            float v1 = __shfl_sync(0xffffffffu, p1, src2);
            float w0 = __shfl_sync(0xffffffffu, p2, src1);
            float w1 = __shfl_sync(0xffffffffu, p3, src1);
            float x0 = __shfl_sync(0xffffffffu, p2, src2);
            float x1 = __shfl_sync(0xffffffffu, p3, src2);
            float pa[4];
            pa[0] = tf32r(odd ? u1 : u0);
            pa[1] = tf32r(odd ? w1 : w0);
            pa[2] = tf32r(odd ? v1 : v0);
            pa[3] = tf32r(odd ? x1 : x0);
            #pragma unroll
            for (int nt = 0; nt < 8; nt++) {
                float bfr[2] = { Vs[kt*8 + q][nt*8 + gp], Vs[kt*8 + q + 4][nt*8 + gp] };
                mma8(oacc[nt], pa, bfr);
            }
        }
    }

    float inv0 = 1.f / l0, inv1 = 1.f / l1;
    size_t r0 = ((size_t)b * Tt + t_r0) * DM + h * DH;
    size_t r1 = ((size_t)b * Tt + t_r1) * DM + h * DH;
    #pragma unroll
    for (int nt = 0; nt < 8; nt++) {
        int d = nt*8 + q*2;
        bsplit(oacc[nt][0] * inv0, g_ctxh[r0 + d],     g_ctxl[r0 + d]);
        bsplit(oacc[nt][1] * inv0, g_ctxh[r0 + d + 1], g_ctxl[r0 + d + 1]);
        bsplit(oacc[nt][2] * inv1, g_ctxh[r1 + d],     g_ctxl[r1 + d]);
        bsplit(oacc[nt][3] * inv1, g_ctxh[r1 + d + 1], g_ctxl[r1 + d + 1]);
    }
}

// ---------------- launch ----------------------------------------------------------------
extern "C" void kernel_launch(void* const* d_in, const int* in_sizes, int n_in,
                              void* d_out, int out_size) {
    const float* x  = (const float*)d_in[0];
    const float* wq = (const float*)d_in[1];
    const float* wk = (const float*)d_in[2];
    const float* wv = (const float*)d_in[3];
    const float* wp = (const float*)d_in[4];
    float* out = (float*)d_out;

    k_split_x <<<(size_t)(Bb*Tt*DM) / 256, 256>>>(x);
    k_gatherc <<<(size_t)(Bb*SS*DM) / 256, 256>>>(x);
    k_split_wq<<<(size_t)(DM*DM)  / 256, 256>>>(wq);
    k_split_wk<<<(size_t)(512*DM) / 256, 256>>>(wk);
    k_split_wv<<<(size_t)(512*DM) / 256, 256>>>(wv);
    k_split_wp<<<(size_t)(DM*DM)  / 256, 256>>>(wp);

    k_gemm_q <<<dim3(DM / 128, (Bb * Tt) / 128), 256>>>();
    k_gemm_kv<<<dim3(1024 / 128, (Bb * SS + 127) / 128), 256>>>();

    k_rope_q<<<(Bb * Tt * NH * 32) / 256, 256>>>();
    k_rope_k<<<(Bb * SS * NKV * 32) / 256, 256>>>();
    k_perm_v<<<(Bb * SS * NKV * DH) / 256, 256>>>();

    k_flash<<<dim3(Tt / 128, Bb * NH), 256>>>();

    k_proj<<<dim3(DM / 128, (Bb * Tt) / 128), 256>>>(out);
}

// round 7
// speedup vs baseline: 2.9904x; 1.0055x over previous
#include <cuda_runtime.h>
#include <cuda_bf16.h>
#include <math.h>

#define Bb 2
#define Tt 4096
#define DM 2048
#define NH 32
#define NKV 8
#define DH 64
#define GRP 4
#define SS 1028
#define SINKN 4
#define POS_SHIFT 3068

// ---------------- scratch (all 16B-aligned) --------------------------------------
__device__ __align__(16) __nv_bfloat16 g_xh  [(size_t)Bb*Tt*DM];
__device__ __align__(16) __nv_bfloat16 g_xl  [(size_t)Bb*Tt*DM];
__device__ __align__(16) __nv_bfloat16 g_xsh [(size_t)Bb*SS*DM];
__device__ __align__(16) __nv_bfloat16 g_xsl [(size_t)Bb*SS*DM];
__device__ __align__(16) __nv_bfloat16 g_wqh [(size_t)DM*DM];
__device__ __align__(16) __nv_bfloat16 g_wql [(size_t)DM*DM];
__device__ __align__(16) __nv_bfloat16 g_wkvh[(size_t)1024*DM];
__device__ __align__(16) __nv_bfloat16 g_wkvl[(size_t)1024*DM];
__device__ __align__(16) __nv_bfloat16 g_wph [(size_t)DM*DM];
__device__ __align__(16) __nv_bfloat16 g_wpl [(size_t)DM*DM];
__device__ __align__(16) __nv_bfloat16 g_ctxh[(size_t)Bb*Tt*DM];
__device__ __align__(16) __nv_bfloat16 g_ctxl[(size_t)Bb*Tt*DM];
__device__ __align__(16) float g_qtmp [(size_t)Bb*Tt*DM];
__device__ __align__(16) float g_kvtmp[(size_t)Bb*SS*1024];
__device__ __align__(16) float g_Qh   [(size_t)Bb*NH *Tt*DH];
__device__ __align__(16) float g_Kh   [(size_t)Bb*NKV*SS*DH];
__device__ __align__(16) float g_Vh   [(size_t)Bb*NKV*SS*DH];

// ---------------- helpers ----------------------------------------------------------
__device__ __forceinline__ float tf32r(float x) {
    unsigned u; asm("cvt.rna.tf32.f32 %0, %1;" : "=r"(u) : "f"(x));
    return __uint_as_float(u);
}
__device__ __forceinline__ void mma8(float c[4], const float a[4], const float b[2]) {
    asm volatile("mma.sync.aligned.m16n8k8.row.col.f32.tf32.tf32.f32 "
        "{%0,%1,%2,%3},{%4,%5,%6,%7},{%8,%9},{%0,%1,%2,%3};"
        : "+f"(c[0]), "+f"(c[1]), "+f"(c[2]), "+f"(c[3])
        : "r"(__float_as_uint(a[0])), "r"(__float_as_uint(a[1])),
          "r"(__float_as_uint(a[2])), "r"(__float_as_uint(a[3])),
          "r"(__float_as_uint(b[0])), "r"(__float_as_uint(b[1])));
}
__device__ __forceinline__ void mma16(float c[4], const unsigned a[4], const unsigned b[2]) {
    asm volatile("mma.sync.aligned.m16n8k16.row.col.f32.bf16.bf16.f32 "
        "{%0,%1,%2,%3},{%4,%5,%6,%7},{%8,%9},{%0,%1,%2,%3};"
        : "+f"(c[0]), "+f"(c[1]), "+f"(c[2]), "+f"(c[3])
        : "r"(a[0]), "r"(a[1]), "r"(a[2]), "r"(a[3]), "r"(b[0]), "r"(b[1]));
}
__device__ __forceinline__ void bsplit(float v, __nv_bfloat16& h, __nv_bfloat16& l) {
    h = __float2bfloat16_rn(v);
    l = __float2bfloat16_rn(v - __bfloat162float(h));
}
__device__ __forceinline__ unsigned smem_u32(const void* p) {
    return (unsigned)__cvta_generic_to_shared(p);
}
__device__ __forceinline__ void cpa16(unsigned dst, const void* src) {
    asm volatile("cp.async.cg.shared.global [%0], [%1], 16;" :: "r"(dst), "l"(src));
}

// ---------------- split kernels (destinations named in DEVICE code) -----------------
__global__ void k_split_x(const float* __restrict__ s) {
    size_t i = (size_t)blockIdx.x * blockDim.x + threadIdx.x;
    bsplit(s[i], g_xh[i], g_xl[i]);
}
__global__ void k_split_wq(const float* __restrict__ s) {
    size_t i = (size_t)blockIdx.x * blockDim.x + threadIdx.x;
    bsplit(s[i], g_wqh[i], g_wql[i]);
}
__global__ void k_split_wk(const float* __restrict__ s) {
    size_t i = (size_t)blockIdx.x * blockDim.x + threadIdx.x;
    bsplit(s[i], g_wkvh[i], g_wkvl[i]);
}
__global__ void k_split_wv(const float* __restrict__ s) {
    size_t i = (size_t)blockIdx.x * blockDim.x + threadIdx.x;
    bsplit(s[i], g_wkvh[(size_t)512*DM + i], g_wkvl[(size_t)512*DM + i]);
}
__global__ void k_split_wp(const float* __restrict__ s) {
    size_t i = (size_t)blockIdx.x * blockDim.x + threadIdx.x;
    bsplit(s[i], g_wph[i], g_wpl[i]);
}
__global__ void k_gatherc(const float* __restrict__ x) {
    size_t idx = (size_t)blockIdx.x * blockDim.x + threadIdx.x;
    int c = idx % DM;
    int j = (idx / DM) % SS;
    int b = idx / ((size_t)DM * SS);
    int pos = (j < SINKN) ? j : j + POS_SHIFT;
    bsplit(x[((size_t)b * Tt + pos) * DM + c], g_xsh[idx], g_xsl[idx]);
}

// ---------------- split-bf16 GEMM, cp.async 3-stage pipeline -------------------------
// C[M,N] = (Ah+Al)*(Wh)^T + Ah*(Wl)^T, fp32 acc; 128x128 tile, BK=16, 8 warps.
#define SK  24
#define SKU 12

__device__ __forceinline__ void gemm_bf16_dev(
    const __nv_bfloat16* __restrict__ Ah_, const __nv_bfloat16* __restrict__ Al_,
    const __nv_bfloat16* __restrict__ Wh_, const __nv_bfloat16* __restrict__ Wl_,
    float* __restrict__ C, int M, int N, int K)
{
    __shared__ __align__(16) __nv_bfloat16 sm[3][4][128 * SK];   // 36 KB
    int tid = threadIdx.x, lane = tid & 31, wid = tid >> 5;
    int wm = wid >> 1, wn = wid & 1, gp = lane >> 2, q = lane & 3;
    int bm = blockIdx.y * 128, bn = blockIdx.x * 128;

    float acc[2][8][4];
    #pragma unroll
    for (int mt = 0; mt < 2; mt++)
        #pragma unroll
        for (int nt = 0; nt < 8; nt++)
            #pragma unroll
            for (int i = 0; i < 4; i++) acc[mt][nt][i] = 0.f;

    int lr = tid >> 1, lc = (tid & 1) * 8;
    int arow = bm + lr; if (arow > M - 1) arow = M - 1;
    int brow = bn + lr; if (brow > N - 1) brow = N - 1;
    const __nv_bfloat16* gsrc[4] = {
        Ah_ + (size_t)arow * K + lc, Al_ + (size_t)arow * K + lc,
        Wh_ + (size_t)brow * K + lc, Wl_ + (size_t)brow * K + lc };
    unsigned sd[3][4];
    #pragma unroll
    for (int s = 0; s < 3; s++)
        #pragma unroll
        for (int p = 0; p < 4; p++)
            sd[s][p] = smem_u32(&sm[s][p][lr * SK + lc]);

    int iters = K / 16;
    // prologue: stages 0, 1
    #pragma unroll
    for (int p = 0; p < 4; p++) cpa16(sd[0][p], gsrc[p]);
    asm volatile("cp.async.commit_group;");
    #pragma unroll
    for (int p = 0; p < 4; p++) cpa16(sd[1][p], gsrc[p] + 16);
    asm volatile("cp.async.commit_group;");

    for (int i = 0; i < iters; i++) {
        if (i == iters - 1) asm volatile("cp.async.wait_group 0;");
        else                asm volatile("cp.async.wait_group 1;");
        __syncthreads();

        // issue load for stage i+2 (slot (i+2)%3 == (i-1)%3, freed by compute(i-1))
        if (i + 2 < iters) {
            int s = (i + 2) % 3, k0 = (i + 2) * 16;
            #pragma unroll
            for (int p = 0; p < 4; p++) cpa16(sd[s][p], gsrc[p] + k0);
            asm volatile("cp.async.commit_group;");
        }

        int cur = i % 3;
        const unsigned* uAh = (const unsigned*)&sm[cur][0][0];
        const unsigned* uAl = (const unsigned*)&sm[cur][1][0];
        const unsigned* uBh = (const unsigned*)&sm[cur][2][0];
        const unsigned* uBl = (const unsigned*)&sm[cur][3][0];

        unsigned ah[2][4], al[2][4];
        #pragma unroll
        for (int mt = 0; mt < 2; mt++) {
            int r = wm * 32 + mt * 16 + gp;
            ah[mt][0] = uAh[r * SKU + q];           al[mt][0] = uAl[r * SKU + q];
            ah[mt][1] = uAh[(r + 8) * SKU + q];     al[mt][1] = uAl[(r + 8) * SKU + q];
            ah[mt][2] = uAh[r * SKU + q + 4];       al[mt][2] = uAl[r * SKU + q + 4];
            ah[mt][3] = uAh[(r + 8) * SKU + q + 4]; al[mt][3] = uAl[(r + 8) * SKU + q + 4];
        }
        #pragma unroll
        for (int nt = 0; nt < 8; nt++) {
            int n = wn * 64 + nt * 8 + gp;
            unsigned bh[2] = { uBh[n * SKU + q], uBh[n * SKU + q + 4] };
            unsigned bl[2] = { uBl[n * SKU + q], uBl[n * SKU + q + 4] };
            #pragma unroll
            for (int mt = 0; mt < 2; mt++) {
                mma16(acc[mt][nt], al[mt], bh);
                mma16(acc[mt][nt], ah[mt], bl);
                mma16(acc[mt][nt], ah[mt], bh);
            }
        }
    }

    #pragma unroll
    for (int mt = 0; mt < 2; mt++) {
        int r = bm + wm * 32 + mt * 16 + gp;
        #pragma unroll
        for (int nt = 0; nt < 8; nt++) {
            int cc = bn + wn * 64 + nt * 8 + q * 2;
            if (r < M) {
                C[(size_t)r * N + cc]     = acc[mt][nt][0];
                C[(size_t)r * N + cc + 1] = acc[mt][nt][1];
            }
            if (r + 8 < M) {
                C[(size_t)(r + 8) * N + cc]     = acc[mt][nt][2];
                C[(size_t)(r + 8) * N + cc + 1] = acc[mt][nt][3];
            }
        }
    }
}

__global__ void __launch_bounds__(256, 2) k_gemm_q() {
    gemm_bf16_dev(g_xh, g_xl, g_wqh, g_wql, g_qtmp, Bb * Tt, DM, DM);
}
__global__ void __launch_bounds__(256, 2) k_gemm_kv() {
    gemm_bf16_dev(g_xsh, g_xsl, g_wkvh, g_wkvl, g_kvtmp, Bb * SS, 1024, DM);
}
__global__ void __launch_bounds__(256, 2) k_proj(float* __restrict__ out) {
    gemm_bf16_dev(g_ctxh, g_ctxl, g_wph, g_wpl, out, Bb * Tt, DM, DM);
}

// ---------------- RoPE + layout permute ----------------------------------------------
__global__ void k_rope_q() {
    size_t idx = (size_t)blockIdx.x * blockDim.x + threadIdx.x;
    int i = idx & 31;
    size_t rest = idx >> 5;
    int h = rest % NH; rest /= NH;
    int t = rest % Tt;
    int b = rest / Tt;
    size_t src = ((size_t)b * Tt + t) * DM + h * DH;
    float x1 = g_qtmp[src + i];
    float x2 = g_qtmp[src + i + 32];
    double inv = pow(10000.0, -(double)i / 32.0);
    double ang = (double)t * inv;
    float c = (float)cos(ang), s = (float)sin(ang);
    size_t o = (((size_t)b * NH + h) * Tt + t) * DH;
    g_Qh[o + i]      = x1 * c - x2 * s;
    g_Qh[o + i + 32] = x2 * c + x1 * s;
}

__global__ void k_rope_k() {
    size_t idx = (size_t)blockIdx.x * blockDim.x + threadIdx.x;
    int i = idx & 31;
    size_t rest = idx >> 5;
    int kh = rest % NKV; rest /= NKV;
    int j = rest % SS;
    int b = rest / SS;
    int pos = (j < SINKN) ? j : j + POS_SHIFT;
    size_t src = ((size_t)b * SS + j) * 1024 + kh * DH;
    float x1 = g_kvtmp[src + i];
    float x2 = g_kvtmp[src + i + 32];
    double inv = pow(10000.0, -(double)i / 32.0);
    double ang = (double)pos * inv;
    float c = (float)cos(ang), s = (float)sin(ang);
    size_t o = (((size_t)b * NKV + kh) * SS + j) * DH;
    g_Kh[o + i]      = x1 * c - x2 * s;
    g_Kh[o + i + 32] = x2 * c + x1 * s;
}

__global__ void k_perm_v() {
    size_t idx = (size_t)blockIdx.x * blockDim.x + threadIdx.x;
    int d = idx & 63;
    size_t rest = idx >> 6;
    int kh = rest % NKV; rest /= NKV;
    int j = rest % SS;
    int b = rest / SS;
    g_Vh[(((size_t)b * NKV + kh) * SS + j) * DH + d] =
        g_kvtmp[((size_t)b * SS + j) * 1024 + 512 + kh * DH + d];
}

// ---------------- fused flash attention (tf32 mma, online softmax) --------------------
__global__ void __launch_bounds__(256, 1) k_flash() {
    __shared__ float Ks[64][68];
    __shared__ float Vs[64][72];
    int tid = threadIdx.x, lane = tid & 31, wid = tid >> 5;
    int gp = lane >> 2, q = lane & 3;
    int t0 = blockIdx.x * 128;
    int z = blockIdx.y;
    int b = z >> 5, h = z & 31, kvh = h >> 2;
    const float* Qp = g_Qh + (size_t)z * Tt * DH;
    const float* Kp = g_Kh + ((size_t)(b * NKV + kvh)) * SS * DH;
    const float* Vp = g_Vh + ((size_t)(b * NKV + kvh)) * SS * DH;

    int t_r0 = t0 + wid * 16 + gp;
    int t_r1 = t_r0 + 8;
    int warp_tmin = t0 + wid * 16;
    int s_end = min(SS, t0 + 128);

    float qa[8][4];
    {
        const float* q0 = Qp + (size_t)t_r0 * DH;
        const float* q1 = Qp + (size_t)t_r1 * DH;
        #pragma unroll
        for (int kk = 0; kk < 8; kk++) {
            qa[kk][0] = tf32r(q0[kk*8 + q]);
            qa[kk][1] = tf32r(q1[kk*8 + q]);
            qa[kk][2] = tf32r(q0[kk*8 + q + 4]);
            qa[kk][3] = tf32r(q1[kk*8 + q + 4]);
        }
    }

    float oacc[8][4];
    #pragma unroll
    for (int nt = 0; nt < 8; nt++)
        #pragma unroll
        for (int i = 0; i < 4; i++) oacc[nt][i] = 0.f;
    float m0 = -1e30f, m1 = -1e30f, l0 = 0.f, l1 = 0.f;

    int src1 = (lane & ~3) | (q >> 1);
    int src2 = src1 + 2;
    bool odd = (q & 1);

    for (int s0 = 0; s0 < s_end; s0 += 64) {
        __syncthreads();
        #pragma unroll
        for (int i = 0; i < 4; i++) {
            int f = i * 256 + tid;
            int r = f >> 4;
            int c = (f & 15) * 4;
            int srow = s0 + r;
            float4 kv = {0,0,0,0}, vv = {0,0,0,0};
            if (srow < SS) {
                kv = *(const float4*)(Kp + (size_t)srow * DH + c);
                vv = *(const float4*)(Vp + (size_t)srow * DH + c);
            }
            Ks[r][c+0] = tf32r(kv.x); Ks[r][c+1] = tf32r(kv.y);
            Ks[r][c+2] = tf32r(kv.z); Ks[r][c+3] = tf32r(kv.w);
            Vs[r][c+0] = tf32r(vv.x); Vs[r][c+1] = tf32r(vv.y);
            Vs[r][c+2] = tf32r(vv.z); Vs[r][c+3] = tf32r(vv.w);
        }
        __syncthreads();

        float sacc[8][4];
        #pragma unroll
        for (int nt = 0; nt < 8; nt++)
            #pragma unroll
            for (int i = 0; i < 4; i++) sacc[nt][i] = 0.f;
        #pragma unroll
        for (int kk = 0; kk < 8; kk++) {
            #pragma unroll
            for (int nt = 0; nt < 8; nt++) {
                float bfr[2] = { Ks[nt*8 + gp][kk*8 + q], Ks[nt*8 + gp][kk*8 + q + 4] };
                mma8(sacc[nt], qa[kk], bfr);
            }
        }

        bool nomask = (s0 + 63 <= warp_tmin) && (s0 + 64 <= SS);
        if (nomask) {
            #pragma unroll
            for (int nt = 0; nt < 8; nt++)
                #pragma unroll
                for (int i = 0; i < 4; i++) sacc[nt][i] *= 0.125f;
        } else {
            #pragma unroll
            for (int nt = 0; nt < 8; nt++) {
                int j = s0 + nt*8 + q*2;
                sacc[nt][0] = (j     <= t_r0 && j     < SS) ? sacc[nt][0]*0.125f : -1e30f;
                sacc[nt][1] = (j + 1 <= t_r0 && j + 1 < SS) ? sacc[nt][1]*0.125f : -1e30f;
                sacc[nt][2] = (j     <= t_r1 && j     < SS) ? sacc[nt][2]*0.125f : -1e30f;
                sacc[nt][3] = (j + 1 <= t_r1 && j + 1 < SS) ? sacc[nt][3]*0.125f : -1e30f;
            }
        }

        float mx0 = -1e30f, mx1 = -1e30f;
        #pragma unroll
        for (int nt = 0; nt < 8; nt++) {
            mx0 = fmaxf(mx0, fmaxf(sacc[nt][0], sacc[nt][1]));
            mx1 = fmaxf(mx1, fmaxf(sacc[nt][2], sacc[nt][3]));
        }
        mx0 = fmaxf(mx0, __shfl_xor_sync(0xffffffffu, mx0, 1));
        mx0 = fmaxf(mx0, __shfl_xor_sync(0xffffffffu, mx0, 2));
        mx1 = fmaxf(mx1, __shfl_xor_sync(0xffffffffu, mx1, 1));
        mx1 = fmaxf(mx1, __shfl_xor_sync(0xffffffffu, mx1, 2));
        float mn0 = fmaxf(m0, mx0), mn1 = fmaxf(m1, mx1);
        float al0 = __expf(m0 - mn0), al1 = __expf(m1 - mn1);
        float rs0 = 0.f, rs1 = 0.f;
        #pragma unroll
        for (int nt = 0; nt < 8; nt++) {
            float p0 = __expf(sacc[nt][0] - mn0); sacc[nt][0] = p0; rs0 += p0;
            float p1 = __expf(sacc[nt][1] - mn0); sacc[nt][1] = p1; rs0 += p1;
            float p2 = __expf(sacc[nt][2] - mn1); sacc[nt][2] = p2; rs1 += p2;
            float p3 = __expf(sacc[nt][3] - mn1); sacc[nt][3] = p3; rs1 += p3;
        }
        rs0 += __shfl_xor_sync(0xffffffffu, rs0, 1);
        rs0 += __shfl_xor_sync(0xffffffffu, rs0, 2);
        rs1 += __shfl_xor_sync(0xffffffffu, rs1, 1);
        rs1 += __shfl_xor_sync(0xffffffffu, rs1, 2);
        l0 = l0 * al0 + rs0;
        l1 = l1 * al1 + rs1;
        m0 = mn0; m1 = mn1;
        #pragma unroll
        for (int nt = 0; nt < 8; nt++) {
            oacc[nt][0] *= al0; oacc[nt][1] *= al0;
            oacc[nt][2] *= al1; oacc[nt][3] *= al1;
        }

        #pragma unroll
        for (int kt = 0; kt < 8; kt++) {
            float p0 = sacc[kt][0], p1 = sacc[kt][1], p2 = sacc[kt][2], p3 = sacc[kt][3];
            float u0 = __shfl_sync(0xffffffffu, p0, src1);
            float u1 = __shfl_sync(0xffffffffu, p1, src1);
            float v0 = __shfl_sync(0xffffffffu, p0, src2);
            float v1 = __shfl_sync(0xffffffffu, p1, src2);
            float w0 = __shfl_sync(0xffffffffu, p2, src1);
            float w1 = __shfl_sync(0xffffffffu, p3, src1);
            float x0 = __shfl_sync(0xffffffffu, p2, src2);
            float x1 = __shfl_sync(0xffffffffu, p3, src2);
            float pa[4];
            pa[0] = tf32r(odd ? u1 : u0);
            pa[1] = tf32r(odd ? w1 : w0);
            pa[2] = tf32r(odd ? v1 : v0);
            pa[3] = tf32r(odd ? x1 : x0);
            #pragma unroll
            for (int nt = 0; nt < 8; nt++) {
                float bfr[2] = { Vs[kt*8 + q][nt*8 + gp], Vs[kt*8 + q + 4][nt*8 + gp] };
                mma8(oacc[nt], pa, bfr);
            }
        }
    }

    float inv0 = 1.f / l0, inv1 = 1.f / l1;
    size_t r0 = ((size_t)b * Tt + t_r0) * DM + h * DH;
    size_t r1 = ((size_t)b * Tt + t_r1) * DM + h * DH;
    #pragma unroll
    for (int nt = 0; nt < 8; nt++) {
        int d = nt*8 + q*2;
        bsplit(oacc[nt][0] * inv0, g_ctxh[r0 + d],     g_ctxl[r0 + d]);
        bsplit(oacc[nt][1] * inv0, g_ctxh[r0 + d + 1], g_ctxl[r0 + d + 1]);
        bsplit(oacc[nt][2] * inv1, g_ctxh[r1 + d],     g_ctxl[r1 + d]);
        bsplit(oacc[nt][3] * inv1, g_ctxh[r1 + d + 1], g_ctxl[r1 + d + 1]);
    }
}

// ---------------- launch ----------------------------------------------------------------
extern "C" void kernel_launch(void* const* d_in, const int* in_sizes, int n_in,
                              void* d_out, int out_size) {
    const float* x  = (const float*)d_in[0];
    const float* wq = (const float*)d_in[1];
    const float* wk = (const float*)d_in[2];
    const float* wv = (const float*)d_in[3];
    const float* wp = (const float*)d_in[4];
    float* out = (float*)d_out;

    k_split_x <<<(size_t)(Bb*Tt*DM) / 256, 256>>>(x);
    k_gatherc <<<(size_t)(Bb*SS*DM) / 256, 256>>>(x);
    k_split_wq<<<(size_t)(DM*DM)  / 256, 256>>>(wq);
    k_split_wk<<<(size_t)(512*DM) / 256, 256>>>(wk);
    k_split_wv<<<(size_t)(512*DM) / 256, 256>>>(wv);
    k_split_wp<<<(size_t)(DM*DM)  / 256, 256>>>(wp);

    k_gemm_q <<<dim3(DM / 128, (Bb * Tt) / 128), 256>>>();
    k_gemm_kv<<<dim3(1024 / 128, (Bb * SS + 127) / 128), 256>>>();

    k_rope_q<<<(Bb * Tt * NH * 32) / 256, 256>>>();
    k_rope_k<<<(Bb * SS * NKV * 32) / 256, 256>>>();
    k_perm_v<<<(Bb * SS * NKV * DH) / 256, 256>>>();

    k_flash<<<dim3(Tt / 128, Bb * NH), 256>>>();

    k_proj<<<dim3(DM / 128, (Bb * Tt) / 128), 256>>>(out);
}

// round 8
// speedup vs baseline: 4.0699x; 1.3610x over previous
#include <cuda_runtime.h>
#include <cuda_fp16.h>
#include <math.h>

#define Bb 2
#define Tt 4096
#define DM 2048
#define NH 32
#define NKV 8
#define DH 64
#define SS 1028
#define SINKN 4
#define POS_SHIFT 3068
#define VSP 1088   // padded s-dim of g_Vt

// ---------------- scratch (16B-aligned) --------------------------------------------
__device__ __align__(16) __half g_xh  [(size_t)Bb*Tt*DM];
__device__ __align__(16) __half g_xsh [(size_t)Bb*SS*DM];
__device__ __align__(16) __half g_wqh [(size_t)DM*DM];
__device__ __align__(16) __half g_wkvh[(size_t)1024*DM];
__device__ __align__(16) __half g_wph [(size_t)DM*DM];
__device__ __align__(16) __half g_ctxh[(size_t)Bb*Tt*DM];
__device__ __align__(16) float  g_qtmp [(size_t)Bb*Tt*DM];
__device__ __align__(16) float  g_kvtmp[(size_t)Bb*SS*1024];
__device__ __align__(16) __half g_Qh [(size_t)Bb*NH*Tt*DH];
__device__ __align__(16) __half g_Kh [(size_t)Bb*NKV*SS*DH];
__device__ __align__(16) __half g_Vt [(size_t)Bb*NKV*DH*VSP];  // [bk][d][s], s padded

// ---------------- helpers ------------------------------------------------------------
__device__ __forceinline__ void mma16h(float c[4], const unsigned a[4], const unsigned b[2]) {
    asm volatile("mma.sync.aligned.m16n8k16.row.col.f32.f16.f16.f32 "
        "{%0,%1,%2,%3},{%4,%5,%6,%7},{%8,%9},{%0,%1,%2,%3};"
        : "+f"(c[0]), "+f"(c[1]), "+f"(c[2]), "+f"(c[3])
        : "r"(a[0]), "r"(a[1]), "r"(a[2]), "r"(a[3]), "r"(b[0]), "r"(b[1]));
}
__device__ __forceinline__ unsigned packh2(float lo, float hi) {
    __half2 h = __floats2half2_rn(lo, hi);
    return *reinterpret_cast<unsigned*>(&h);
}
__device__ __forceinline__ unsigned smem_u32(const void* p) {
    return (unsigned)__cvta_generic_to_shared(p);
}
__device__ __forceinline__ void cpa16(unsigned dst, const void* src) {
    asm volatile("cp.async.cg.shared.global [%0], [%1], 16;" :: "r"(dst), "l"(src));
}

// ---------------- split / gather (fp16 single plane) ----------------------------------
__global__ void k_split_x(const float* __restrict__ s) {
    size_t i = (size_t)blockIdx.x * blockDim.x + threadIdx.x;
    g_xh[i] = __float2half_rn(s[i]);
}
__global__ void k_split_wq(const float* __restrict__ s) {
    size_t i = (size_t)blockIdx.x * blockDim.x + threadIdx.x;
    g_wqh[i] = __float2half_rn(s[i]);
}
__global__ void k_split_wk(const float* __restrict__ s) {
    size_t i = (size_t)blockIdx.x * blockDim.x + threadIdx.x;
    g_wkvh[i] = __float2half_rn(s[i]);
}
__global__ void k_split_wv(const float* __restrict__ s) {
    size_t i = (size_t)blockIdx.x * blockDim.x + threadIdx.x;
    g_wkvh[(size_t)512*DM + i] = __float2half_rn(s[i]);
}
__global__ void k_split_wp(const float* __restrict__ s) {
    size_t i = (size_t)blockIdx.x * blockDim.x + threadIdx.x;
    g_wph[i] = __float2half_rn(s[i]);
}
__global__ void k_gatherc(const float* __restrict__ x) {
    size_t idx = (size_t)blockIdx.x * blockDim.x + threadIdx.x;
    int c = idx % DM;
    int j = (idx / DM) % SS;
    int b = idx / ((size_t)DM * SS);
    int pos = (j < SINKN) ? j : j + POS_SHIFT;
    g_xsh[idx] = __float2half_rn(x[((size_t)b * Tt + pos) * DM + c]);
}

// ---------------- fp16 GEMM: C[M,N] = A[M,K] * W[N,K]^T, cp.async 3-stage -------------
// 128x128 tile, BK=16, 8 warps (4x2), warp tile 32x64, 16 mma16 per warp per iter.
#define SK2  24   // smem row stride (fp16)
#define SKU2 12   // in uints

__device__ __forceinline__ void gemm_fp16_dev(
    const __half* __restrict__ A_, const __half* __restrict__ W_,
    float* __restrict__ C, int M, int N, int K)
{
    __shared__ __align__(16) __half sm[3][2][128 * SK2];   // 36 KB
    int tid = threadIdx.x, lane = tid & 31, wid = tid >> 5;
    int wm = wid >> 1, wn = wid & 1, gp = lane >> 2, q = lane & 3;
    int bm = blockIdx.y * 128, bn = blockIdx.x * 128;

    float acc[2][8][4];
    #pragma unroll
    for (int mt = 0; mt < 2; mt++)
        #pragma unroll
        for (int nt = 0; nt < 8; nt++)
            #pragma unroll
            for (int i = 0; i < 4; i++) acc[mt][nt][i] = 0.f;

    int lr = tid >> 1, lseg = (tid & 1) * 8;
    int arow = bm + lr; if (arow > M - 1) arow = M - 1;
    int brow = bn + lr; if (brow > N - 1) brow = N - 1;
    const __half* ga = A_ + (size_t)arow * K + lseg;
    const __half* gb = W_ + (size_t)brow * K + lseg;
    unsigned sda[3], sdb[3];
    #pragma unroll
    for (int s = 0; s < 3; s++) {
        sda[s] = smem_u32(&sm[s][0][lr * SK2 + lseg]);
        sdb[s] = smem_u32(&sm[s][1][lr * SK2 + lseg]);
    }

    int iters = K / 16;
    cpa16(sda[0], ga);      cpa16(sdb[0], gb);
    asm volatile("cp.async.commit_group;");
    cpa16(sda[1], ga + 16); cpa16(sdb[1], gb + 16);
    asm volatile("cp.async.commit_group;");

    for (int i = 0; i < iters; i++) {
        if (i == iters - 1) asm volatile("cp.async.wait_group 0;");
        else                asm volatile("cp.async.wait_group 1;");
        __syncthreads();

        if (i + 2 < iters) {
            int s = (i + 2) % 3, k0 = (i + 2) * 16;
            cpa16(sda[s], ga + k0);
            cpa16(sdb[s], gb + k0);
            asm volatile("cp.async.commit_group;");
        }

        int cur = i % 3;
        const unsigned* uA = (const unsigned*)&sm[cur][0][0];
        const unsigned* uB = (const unsigned*)&sm[cur][1][0];

        unsigned a[2][4];
        #pragma unroll
        for (int mt = 0; mt < 2; mt++) {
            int r = wm * 32 + mt * 16 + gp;
            a[mt][0] = uA[r * SKU2 + q];
            a[mt][1] = uA[(r + 8) * SKU2 + q];
            a[mt][2] = uA[r * SKU2 + q + 4];
            a[mt][3] = uA[(r + 8) * SKU2 + q + 4];
        }
        #pragma unroll
        for (int nt = 0; nt < 8; nt++) {
            int n = wn * 64 + nt * 8 + gp;
            unsigned b[2] = { uB[n * SKU2 + q], uB[n * SKU2 + q + 4] };
            mma16h(acc[0][nt], a[0], b);
            mma16h(acc[1][nt], a[1], b);
        }
    }

    #pragma unroll
    for (int mt = 0; mt < 2; mt++) {
        int r = bm + wm * 32 + mt * 16 + gp;
        #pragma unroll
        for (int nt = 0; nt < 8; nt++) {
            int cc = bn + wn * 64 + nt * 8 + q * 2;
            if (r < M) {
                C[(size_t)r * N + cc]     = acc[mt][nt][0];
                C[(size_t)r * N + cc + 1] = acc[mt][nt][1];
            }
            if (r + 8 < M) {
                C[(size_t)(r + 8) * N + cc]     = acc[mt][nt][2];
                C[(size_t)(r + 8) * N + cc + 1] = acc[mt][nt][3];
            }
        }
    }
}

__global__ void __launch_bounds__(256, 2) k_gemm_q() {
    gemm_fp16_dev(g_xh, g_wqh, g_qtmp, Bb * Tt, DM, DM);
}
__global__ void __launch_bounds__(256, 2) k_gemm_kv() {
    gemm_fp16_dev(g_xsh, g_wkvh, g_kvtmp, Bb * SS, 1024, DM);
}
__global__ void __launch_bounds__(256, 2) k_proj(float* __restrict__ out) {
    gemm_fp16_dev(g_ctxh, g_wph, out, Bb * Tt, DM, DM);
}

// ---------------- RoPE + V permute (fp16 outputs) --------------------------------------
__global__ void k_rope_q() {
    size_t idx = (size_t)blockIdx.x * blockDim.x + threadIdx.x;
    int i = idx & 31;
    size_t rest = idx >> 5;
    int h = rest % NH; rest /= NH;
    int t = rest % Tt;
    int b = rest / Tt;
    size_t src = ((size_t)b * Tt + t) * DM + h * DH;
    float x1 = g_qtmp[src + i];
    float x2 = g_qtmp[src + i + 32];
    double inv = pow(10000.0, -(double)i / 32.0);
    double ang = (double)t * inv;
    float c = (float)cos(ang), s = (float)sin(ang);
    size_t o = (((size_t)b * NH + h) * Tt + t) * DH;
    g_Qh[o + i]      = __float2half_rn(x1 * c - x2 * s);
    g_Qh[o + i + 32] = __float2half_rn(x2 * c + x1 * s);
}

__global__ void k_rope_k() {
    size_t idx = (size_t)blockIdx.x * blockDim.x + threadIdx.x;
    int i = idx & 31;
    size_t rest = idx >> 5;
    int kh = rest % NKV; rest /= NKV;
    int j = rest % SS;
    int b = rest / SS;
    int pos = (j < SINKN) ? j : j + POS_SHIFT;
    size_t src = ((size_t)b * SS + j) * 1024 + kh * DH;
    float x1 = g_kvtmp[src + i];
    float x2 = g_kvtmp[src + i + 32];
    double inv = pow(10000.0, -(double)i / 32.0);
    double ang = (double)pos * inv;
    float c = (float)cos(ang), s = (float)sin(ang);
    size_t o = (((size_t)b * NKV + kh) * SS + j) * DH;
    g_Kh[o + i]      = __float2half_rn(x1 * c - x2 * s);
    g_Kh[o + i + 32] = __float2half_rn(x2 * c + x1 * s);
}

// V transposed to [bk][d][s] with zero-padded s (so flash never masks V loads)
__global__ void k_perm_v() {
    int bkd = blockIdx.x;               // (b*NKV+kh)*64 + d
    int d  = bkd & 63;
    int bk = bkd >> 6;
    int b  = bk >> 3, kh = bk & 7;
    for (int s = threadIdx.x; s < VSP; s += 256) {
        float v = 0.f;
        if (s < SS) v = g_kvtmp[((size_t)b * SS + s) * 1024 + 512 + kh * 64 + d];
        g_Vt[((size_t)bk * DH + d) * VSP + s] = __float2half_rn(v);
    }
}

// ---------------- fused flash attention (fp16 mma16, online softmax) --------------------
__global__ void __launch_bounds__(256, 2) k_flash() {
    __shared__ __align__(16) __half Ks [64 * 72];   // [s][d], stride 72 fp16
    __shared__ __align__(16) __half Vts[64 * 72];   // [d][s], stride 72 fp16
    int tid = threadIdx.x, lane = tid & 31, wid = tid >> 5;
    int gp = lane >> 2, q = lane & 3;
    int t0 = blockIdx.x * 128;
    int z = blockIdx.y;
    int b = z >> 5, h = z & 31, kvh = h >> 2;
    int bk = b * NKV + kvh;
    const __half* Qp = g_Qh + (size_t)z * Tt * DH;
    const __half* Kp = g_Kh + (size_t)bk * SS * DH;
    const __half* Vp = g_Vt + (size_t)bk * DH * VSP;

    int t_r0 = t0 + wid * 16 + gp;
    int t_r1 = t_r0 + 8;
    int warp_tmin = t0 + wid * 16;
    int s_end = min(SS, t0 + 128);

    // Q fragments (fp16 pairs), loaded once: qa[kk] covers k = kk*16..kk*16+15
    unsigned qa[4][4];
    {
        const unsigned* uQ0 = (const unsigned*)(Qp + (size_t)t_r0 * DH);
        const unsigned* uQ1 = (const unsigned*)(Qp + (size_t)t_r1 * DH);
        #pragma unroll
        for (int kk = 0; kk < 4; kk++) {
            qa[kk][0] = uQ0[kk * 8 + q];
            qa[kk][1] = uQ1[kk * 8 + q];
            qa[kk][2] = uQ0[kk * 8 + q + 4];
            qa[kk][3] = uQ1[kk * 8 + q + 4];
        }
    }

    float oacc[8][4];
    #pragma unroll
    for (int nt = 0; nt < 8; nt++)
        #pragma unroll
        for (int i = 0; i < 4; i++) oacc[nt][i] = 0.f;
    float m0 = -1e30f, m1 = -1e30f, l0 = 0.f, l1 = 0.f;

    const unsigned* uKs = (const unsigned*)Ks;
    const unsigned* uVt = (const unsigned*)Vts;

    for (int s0 = 0; s0 < s_end; s0 += 64) {
        __syncthreads();
        #pragma unroll
        for (int i = 0; i < 2; i++) {
            int f = i * 256 + tid;
            int r = f >> 3, sg = (f & 7) * 8;
            uint4 kv = make_uint4(0, 0, 0, 0);
            int srow = s0 + r;
            if (srow < SS) kv = *(const uint4*)(Kp + (size_t)srow * DH + sg);
            *(uint4*)(&Ks[r * 72 + sg]) = kv;
            uint4 vv = *(const uint4*)(Vp + (size_t)r * VSP + s0 + sg);
            *(uint4*)(&Vts[r * 72 + sg]) = vv;
        }
        __syncthreads();

        // S = Q K^T (fp16 k16)
        float sacc[8][4];
        #pragma unroll
        for (int nt = 0; nt < 8; nt++)
            #pragma unroll
            for (int i = 0; i < 4; i++) sacc[nt][i] = 0.f;
        #pragma unroll
        for (int kk = 0; kk < 4; kk++) {
            #pragma unroll
            for (int nt = 0; nt < 8; nt++) {
                unsigned bfr[2] = { uKs[(nt*8 + gp) * 36 + kk*8 + q],
                                    uKs[(nt*8 + gp) * 36 + kk*8 + q + 4] };
                mma16h(sacc[nt], qa[kk], bfr);
            }
        }

        bool nomask = (s0 + 63 <= warp_tmin) && (s0 + 64 <= SS);
        if (nomask) {
            #pragma unroll
            for (int nt = 0; nt < 8; nt++)
                #pragma unroll
                for (int i = 0; i < 4; i++) sacc[nt][i] *= 0.125f;
        } else {
            #pragma unroll
            for (int nt = 0; nt < 8; nt++) {
                int j = s0 + nt*8 + q*2;
                sacc[nt][0] = (j     <= t_r0 && j     < SS) ? sacc[nt][0]*0.125f : -1e30f;
                sacc[nt][1] = (j + 1 <= t_r0 && j + 1 < SS) ? sacc[nt][1]*0.125f : -1e30f;
                sacc[nt][2] = (j     <= t_r1 && j     < SS) ? sacc[nt][2]*0.125f : -1e30f;
                sacc[nt][3] = (j + 1 <= t_r1 && j + 1 < SS) ? sacc[nt][3]*0.125f : -1e30f;
            }
        }

        // online softmax
        float mx0 = -1e30f, mx1 = -1e30f;
        #pragma unroll
        for (int nt = 0; nt < 8; nt++) {
            mx0 = fmaxf(mx0, fmaxf(sacc[nt][0], sacc[nt][1]));
            mx1 = fmaxf(mx1, fmaxf(sacc[nt][2], sacc[nt][3]));
        }
        mx0 = fmaxf(mx0, __shfl_xor_sync(0xffffffffu, mx0, 1));
        mx0 = fmaxf(mx0, __shfl_xor_sync(0xffffffffu, mx0, 2));
        mx1 = fmaxf(mx1, __shfl_xor_sync(0xffffffffu, mx1, 1));
        mx1 = fmaxf(mx1, __shfl_xor_sync(0xffffffffu, mx1, 2));
        float mn0 = fmaxf(m0, mx0), mn1 = fmaxf(m1, mx1);
        float al0 = __expf(m0 - mn0), al1 = __expf(m1 - mn1);
        float rs0 = 0.f, rs1 = 0.f;
        #pragma unroll
        for (int nt = 0; nt < 8; nt++) {
            float p0 = __expf(sacc[nt][0] - mn0); sacc[nt][0] = p0; rs0 += p0;
            float p1 = __expf(sacc[nt][1] - mn0); sacc[nt][1] = p1; rs0 += p1;
            float p2 = __expf(sacc[nt][2] - mn1); sacc[nt][2] = p2; rs1 += p2;
            float p3 = __expf(sacc[nt][3] - mn1); sacc[nt][3] = p3; rs1 += p3;
        }
        rs0 += __shfl_xor_sync(0xffffffffu, rs0, 1);
        rs0 += __shfl_xor_sync(0xffffffffu, rs0, 2);
        rs1 += __shfl_xor_sync(0xffffffffu, rs1, 1);
        rs1 += __shfl_xor_sync(0xffffffffu, rs1, 2);
        l0 = l0 * al0 + rs0;
        l1 = l1 * al1 + rs1;
        m0 = mn0; m1 = mn1;
        #pragma unroll
        for (int nt = 0; nt < 8; nt++) {
            oacc[nt][0] *= al0; oacc[nt][1] *= al0;
            oacc[nt][2] *= al1; oacc[nt][3] *= al1;
        }

        // O += P @ V : P a-frags come directly from sacc (no shuffles with fp16 k16)
        #pragma unroll
        for (int kt = 0; kt < 4; kt++) {
            unsigned pa[4];
            pa[0] = packh2(sacc[2*kt][0],     sacc[2*kt][1]);
            pa[1] = packh2(sacc[2*kt][2],     sacc[2*kt][3]);
            pa[2] = packh2(sacc[2*kt + 1][0], sacc[2*kt + 1][1]);
            pa[3] = packh2(sacc[2*kt + 1][2], sacc[2*kt + 1][3]);
            #pragma unroll
            for (int nt = 0; nt < 8; nt++) {
                unsigned bfr[2] = { uVt[(nt*8 + gp) * 36 + kt*8 + q],
                                    uVt[(nt*8 + gp) * 36 + kt*8 + q + 4] };
                mma16h(oacc[nt], pa, bfr);
            }
        }
    }

    // epilogue: normalize, write fp16 ctx [b][t][h*64+d]
    float inv0 = 1.f / l0, inv1 = 1.f / l1;
    size_t r0 = ((size_t)b * Tt + t_r0) * DM + h * DH;
    size_t r1 = ((size_t)b * Tt + t_r1) * DM + h * DH;
    #pragma unroll
    for (int nt = 0; nt < 8; nt++) {
        int d = nt*8 + q*2;
        g_ctxh[r0 + d]     = __float2half_rn(oacc[nt][0] * inv0);
        g_ctxh[r0 + d + 1] = __float2half_rn(oacc[nt][1] * inv0);
        g_ctxh[r1 + d]     = __float2half_rn(oacc[nt][2] * inv1);
        g_ctxh[r1 + d + 1] = __float2half_rn(oacc[nt][3] * inv1);
    }
}

// ---------------- launch -------------------------------------------------------------------
extern "C" void kernel_launch(void* const* d_in, const int* in_sizes, int n_in,
                              void* d_out, int out_size) {
    const float* x  = (const float*)d_in[0];
    const float* wq = (const float*)d_in[1];
    const float* wk = (const float*)d_in[2];
    const float* wv = (const float*)d_in[3];
    const float* wp = (const float*)d_in[4];
    float* out = (float*)d_out;

    k_split_x <<<(size_t)(Bb*Tt*DM) / 256, 256>>>(x);
    k_gatherc <<<(size_t)(Bb*SS*DM) / 256, 256>>>(x);
    k_split_wq<<<(size_t)(DM*DM)  / 256, 256>>>(wq);
    k_split_wk<<<(size_t)(512*DM) / 256, 256>>>(wk);
    k_split_wv<<<(size_t)(512*DM) / 256, 256>>>(wv);
    k_split_wp<<<(size_t)(DM*DM)  / 256, 256>>>(wp);

    k_gemm_q <<<dim3(DM / 128, (Bb * Tt) / 128), 256>>>();
    k_gemm_kv<<<dim3(1024 / 128, (Bb * SS + 127) / 128), 256>>>();

    k_rope_q<<<(Bb * Tt * NH * 32) / 256, 256>>>();
    k_rope_k<<<(Bb * SS * NKV * 32) / 256, 256>>>();
    k_perm_v<<<Bb * NKV * DH, 256>>>();

    k_flash<<<dim3(Tt / 128, Bb * NH), 256>>>();

    k_proj<<<dim3(DM / 128, (Bb * Tt) / 128), 256>>>(out);
}

// round 9
// speedup vs baseline: 12.5553x; 3.0849x over previous
#include <cuda_runtime.h>
#include <cuda_fp16.h>
#include <math.h>

#define Bb 2
#define Tt 4096
#define DM 2048
#define NH 32
#define NKV 8
#define DH 64
#define SS 1028
#define SINKN 4
#define POS_SHIFT 3068
#define VSP 1088

// ---------------- scratch (16B-aligned) --------------------------------------------
__device__ __align__(16) __half g_xh  [(size_t)Bb*Tt*DM];
__device__ __align__(16) __half g_xsh [(size_t)Bb*SS*DM];
__device__ __align__(16) __half g_wqh [(size_t)DM*DM];
__device__ __align__(16) __half g_wkvh[(size_t)1024*DM];
__device__ __align__(16) __half g_wph [(size_t)DM*DM];
__device__ __align__(16) __half g_ctxh[(size_t)Bb*Tt*DM];
__device__ __align__(16) float  g_qtmp [(size_t)Bb*Tt*DM];
__device__ __align__(16) float  g_kvtmp[(size_t)Bb*SS*1024];
__device__ __align__(16) __half g_Qh [(size_t)Bb*NH*Tt*DH];
__device__ __align__(16) __half g_Kh [(size_t)Bb*NKV*SS*DH];
__device__ __align__(16) __half g_Vt [(size_t)Bb*NKV*DH*VSP];
__device__ __align__(16) float2 g_rtab[(size_t)Tt*32];

// ---------------- helpers ------------------------------------------------------------
__device__ __forceinline__ void mma16h(float c[4], const unsigned a[4], const unsigned b[2]) {
    asm volatile("mma.sync.aligned.m16n8k16.row.col.f32.f16.f16.f32 "
        "{%0,%1,%2,%3},{%4,%5,%6,%7},{%8,%9},{%0,%1,%2,%3};"
        : "+f"(c[0]), "+f"(c[1]), "+f"(c[2]), "+f"(c[3])
        : "r"(a[0]), "r"(a[1]), "r"(a[2]), "r"(a[3]), "r"(b[0]), "r"(b[1]));
}
__device__ __forceinline__ void ldm_x4(unsigned &r0, unsigned &r1, unsigned &r2, unsigned &r3,
                                       unsigned addr) {
    asm volatile("ldmatrix.sync.aligned.m8n8.x4.shared.b16 {%0,%1,%2,%3}, [%4];"
        : "=r"(r0), "=r"(r1), "=r"(r2), "=r"(r3) : "r"(addr));
}
__device__ __forceinline__ unsigned packh2(float lo, float hi) {
    __half2 h = __floats2half2_rn(lo, hi);
    return *reinterpret_cast<unsigned*>(&h);
}
__device__ __forceinline__ unsigned smem_u32(const void* p) {
    return (unsigned)__cvta_generic_to_shared(p);
}
__device__ __forceinline__ void cpa16(unsigned dst, const void* src) {
    asm volatile("cp.async.cg.shared.global [%0], [%1], 16;" :: "r"(dst), "l"(src));
}
__device__ __forceinline__ uint2 pack4(float4 v) {
    __half2 h0 = __floats2half2_rn(v.x, v.y);
    __half2 h1 = __floats2half2_rn(v.z, v.w);
    return make_uint2(*reinterpret_cast<unsigned*>(&h0), *reinterpret_cast<unsigned*>(&h1));
}

// ---------------- RoPE trig table ------------------------------------------------------
__global__ void k_rtab() {
    int idx = blockIdx.x * 256 + threadIdx.x;      // Tt*32
    int i = idx & 31, t = idx >> 5;
    double inv = pow(10000.0, -(double)i / 32.0);
    double ang = (double)t * inv;
    g_rtab[idx] = make_float2((float)cos(ang), (float)sin(ang));
}

// ---------------- split / gather (x4 vectorized) ---------------------------------------
__global__ void k_split_x(const float4* __restrict__ s) {
    size_t i = (size_t)blockIdx.x * blockDim.x + threadIdx.x;
    *(uint2*)&g_xh[i * 4] = pack4(s[i]);
}
__global__ void k_split_wq(const float4* __restrict__ s) {
    size_t i = (size_t)blockIdx.x * blockDim.x + threadIdx.x;
    *(uint2*)&g_wqh[i * 4] = pack4(s[i]);
}
__global__ void k_split_wk(const float4* __restrict__ s) {
    size_t i = (size_t)blockIdx.x * blockDim.x + threadIdx.x;
    *(uint2*)&g_wkvh[i * 4] = pack4(s[i]);
}
__global__ void k_split_wv(const float4* __restrict__ s) {
    size_t i = (size_t)blockIdx.x * blockDim.x + threadIdx.x;
    *(uint2*)&g_wkvh[(size_t)512*DM + i * 4] = pack4(s[i]);
}
__global__ void k_split_wp(const float4* __restrict__ s) {
    size_t i = (size_t)blockIdx.x * blockDim.x + threadIdx.x;
    *(uint2*)&g_wph[i * 4] = pack4(s[i]);
}
__global__ void k_gatherc(const float* __restrict__ x) {
    size_t idx = (size_t)blockIdx.x * blockDim.x + threadIdx.x;   // in float4 units
    int c4 = idx % (DM / 4);
    int j = (idx / (DM / 4)) % SS;
    int b = idx / ((size_t)(DM / 4) * SS);
    int pos = (j < SINKN) ? j : j + POS_SHIFT;
    float4 v = *(const float4*)(x + ((size_t)b * Tt + pos) * DM + c4 * 4);
    *(uint2*)&g_xsh[idx * 4] = pack4(v);
}

// ---------------- fp16 GEMM, cp.async 3-stage + ldmatrix -------------------------------
#define SK2  24
#define SKU2 12

__device__ __forceinline__ void gemm_fp16_dev(
    const __half* __restrict__ A_, const __half* __restrict__ W_,
    float* __restrict__ C, int M, int N, int K)
{
    __shared__ __align__(16) __half sm[3][2][128 * SK2];   // 36 KB
    int tid = threadIdx.x, lane = tid & 31, wid = tid >> 5;
    int wm = wid >> 1, wn = wid & 1, gp = lane >> 2, q = lane & 3;
    int bm = blockIdx.y * 128, bn = blockIdx.x * 128;
    int lmr = lane & 15, lmk = (lane >> 4) * 8;   // ldmatrix lane row / k-offset

    float acc[2][8][4];
    #pragma unroll
    for (int mt = 0; mt < 2; mt++)
        #pragma unroll
        for (int nt = 0; nt < 8; nt++)
            #pragma unroll
            for (int i = 0; i < 4; i++) acc[mt][nt][i] = 0.f;

    int lr = tid >> 1, lseg = (tid & 1) * 8;
    int arow = bm + lr; if (arow > M - 1) arow = M - 1;
    int brow = bn + lr; if (brow > N - 1) brow = N - 1;
    const __half* ga = A_ + (size_t)arow * K + lseg;
    const __half* gb = W_ + (size_t)brow * K + lseg;
    unsigned sda[3], sdb[3];
    #pragma unroll
    for (int s = 0; s < 3; s++) {
        sda[s] = smem_u32(&sm[s][0][lr * SK2 + lseg]);
        sdb[s] = smem_u32(&sm[s][1][lr * SK2 + lseg]);
    }

    int iters = K / 16;
    cpa16(sda[0], ga);      cpa16(sdb[0], gb);
    asm volatile("cp.async.commit_group;");
    cpa16(sda[1], ga + 16); cpa16(sdb[1], gb + 16);
    asm volatile("cp.async.commit_group;");

    for (int i = 0; i < iters; i++) {
        if (i == iters - 1) asm volatile("cp.async.wait_group 0;");
        else                asm volatile("cp.async.wait_group 1;");
        __syncthreads();

        if (i + 2 < iters) {
            int s = (i + 2) % 3, k0 = (i + 2) * 16;
            cpa16(sda[s], ga + k0);
            cpa16(sdb[s], gb + k0);
            asm volatile("cp.async.commit_group;");
        }

        int cur = i % 3;
        unsigned abase = smem_u32(&sm[cur][0][0]);
        unsigned bbase = smem_u32(&sm[cur][1][0]);

        unsigned a[2][4];
        #pragma unroll
        for (int mt = 0; mt < 2; mt++)
            ldm_x4(a[mt][0], a[mt][1], a[mt][2], a[mt][3],
                   abase + ((wm*32 + mt*16 + lmr) * SK2 + lmk) * 2);

        #pragma unroll
        for (int p = 0; p < 4; p++) {
            unsigned r0, r1, r2, r3;
            ldm_x4(r0, r1, r2, r3, bbase + ((wn*64 + p*16 + lmr) * SK2 + lmk) * 2);
            unsigned b0[2] = { r0, r2 }, b1[2] = { r1, r3 };
            mma16h(acc[0][2*p],   a[0], b0);
            mma16h(acc[1][2*p],   a[1], b0);
            mma16h(acc[0][2*p+1], a[0], b1);
            mma16h(acc[1][2*p+1], a[1], b1);
        }
    }

    #pragma unroll
    for (int mt = 0; mt < 2; mt++) {
        int r = bm + wm * 32 + mt * 16 + gp;
        #pragma unroll
        for (int nt = 0; nt < 8; nt++) {
            int cc = bn + wn * 64 + nt * 8 + q * 2;
            if (r < M) {
                C[(size_t)r * N + cc]     = acc[mt][nt][0];
                C[(size_t)r * N + cc + 1] = acc[mt][nt][1];
            }
            if (r + 8 < M) {
                C[(size_t)(r + 8) * N + cc]     = acc[mt][nt][2];
                C[(size_t)(r + 8) * N + cc + 1] = acc[mt][nt][3];
            }
        }
    }
}

__global__ void __launch_bounds__(256, 2) k_gemm_q() {
    gemm_fp16_dev(g_xh, g_wqh, g_qtmp, Bb * Tt, DM, DM);
}
__global__ void __launch_bounds__(256, 2) k_gemm_kv() {
    gemm_fp16_dev(g_xsh, g_wkvh, g_kvtmp, Bb * SS, 1024, DM);
}
__global__ void __launch_bounds__(256, 2) k_proj(float* __restrict__ out) {
    gemm_fp16_dev(g_ctxh, g_wph, out, Bb * Tt, DM, DM);
}

// ---------------- RoPE (table) + V permute ----------------------------------------------
__global__ void k_rope_q() {
    size_t idx = (size_t)blockIdx.x * blockDim.x + threadIdx.x;
    int i = idx & 31;
    size_t rest = idx >> 5;
    int h = rest % NH; rest /= NH;
    int t = rest % Tt;
    int b = rest / Tt;
    size_t src = ((size_t)b * Tt + t) * DM + h * DH;
    float x1 = g_qtmp[src + i];
    float x2 = g_qtmp[src + i + 32];
    float2 cs = g_rtab[t * 32 + i];
    size_t o = (((size_t)b * NH + h) * Tt + t) * DH;
    g_Qh[o + i]      = __float2half_rn(x1 * cs.x - x2 * cs.y);
    g_Qh[o + i + 32] = __float2half_rn(x2 * cs.x + x1 * cs.y);
}

__global__ void k_rope_k() {
    size_t idx = (size_t)blockIdx.x * blockDim.x + threadIdx.x;
    int i = idx & 31;
    size_t rest = idx >> 5;
    int kh = rest % NKV; rest /= NKV;
    int j = rest % SS;
    int b = rest / SS;
    int pos = (j < SINKN) ? j : j + POS_SHIFT;
    size_t src = ((size_t)b * SS + j) * 1024 + kh * DH;
    float x1 = g_kvtmp[src + i];
    float x2 = g_kvtmp[src + i + 32];
    float2 cs = g_rtab[pos * 32 + i];
    size_t o = (((size_t)b * NKV + kh) * SS + j) * DH;
    g_Kh[o + i]      = __float2half_rn(x1 * cs.x - x2 * cs.y);
    g_Kh[o + i + 32] = __float2half_rn(x2 * cs.x + x1 * cs.y);
}

__global__ void k_perm_v() {
    int bkd = blockIdx.x;
    int d  = bkd & 63;
    int bk = bkd >> 6;
    int b  = bk >> 3, kh = bk & 7;
    for (int s = threadIdx.x; s < VSP; s += 256) {
        float v = 0.f;
        if (s < SS) v = g_kvtmp[((size_t)b * SS + s) * 1024 + 512 + kh * 64 + d];
        g_Vt[((size_t)bk * DH + d) * VSP + s] = __float2half_rn(v);
    }
}

// ---------------- fused flash attention (fp16 mma16 + ldmatrix) ---------------------------
__global__ void __launch_bounds__(256, 2) k_flash() {
    __shared__ __align__(16) __half Ks [64 * 72];
    __shared__ __align__(16) __half Vts[64 * 72];
    int tid = threadIdx.x, lane = tid & 31, wid = tid >> 5;
    int gp = lane >> 2, q = lane & 3;
    int lmr = lane & 15, lmk = (lane >> 4) * 8;
    int t0 = blockIdx.x * 128;
    int z = blockIdx.y;
    int b = z >> 5, h = z & 31, kvh = h >> 2;
    int bk = b * NKV + kvh;
    const __half* Qp = g_Qh + (size_t)z * Tt * DH;
    const __half* Kp = g_Kh + (size_t)bk * SS * DH;
    const __half* Vp = g_Vt + (size_t)bk * DH * VSP;

    int t_r0 = t0 + wid * 16 + gp;
    int t_r1 = t_r0 + 8;
    int warp_tmin = t0 + wid * 16;
    int s_end = min(SS, t0 + 128);

    unsigned qa[4][4];
    {
        const unsigned* uQ0 = (const unsigned*)(Qp + (size_t)t_r0 * DH);
        const unsigned* uQ1 = (const unsigned*)(Qp + (size_t)t_r1 * DH);
        #pragma unroll
        for (int kk = 0; kk < 4; kk++) {
            qa[kk][0] = uQ0[kk * 8 + q];
            qa[kk][1] = uQ1[kk * 8 + q];
            qa[kk][2] = uQ0[kk * 8 + q + 4];
            qa[kk][3] = uQ1[kk * 8 + q + 4];
        }
    }

    float oacc[8][4];
    #pragma unroll
    for (int nt = 0; nt < 8; nt++)
        #pragma unroll
        for (int i = 0; i < 4; i++) oacc[nt][i] = 0.f;
    float m0 = -1e30f, m1 = -1e30f, l0 = 0.f, l1 = 0.f;

    unsigned kb = smem_u32(Ks);
    unsigned vb = smem_u32(Vts);

    for (int s0 = 0; s0 < s_end; s0 += 64) {
        __syncthreads();
        #pragma unroll
        for (int i = 0; i < 2; i++) {
            int f = i * 256 + tid;
            int r = f >> 3, sg = (f & 7) * 8;
            uint4 kv = make_uint4(0, 0, 0, 0);
            int srow = s0 + r;
            if (srow < SS) kv = *(const uint4*)(Kp + (size_t)srow * DH + sg);
            *(uint4*)(&Ks[r * 72 + sg]) = kv;
            uint4 vv = *(const uint4*)(Vp + (size_t)r * VSP + s0 + sg);
            *(uint4*)(&Vts[r * 72 + sg]) = vv;
        }
        __syncthreads();

        // S = Q K^T
        float sacc[8][4];
        #pragma unroll
        for (int nt = 0; nt < 8; nt++)
            #pragma unroll
            for (int i = 0; i < 4; i++) sacc[nt][i] = 0.f;
        #pragma unroll
        for (int kk = 0; kk < 4; kk++) {
            #pragma unroll
            for (int p = 0; p < 4; p++) {
                unsigned r0, r1, r2, r3;
                ldm_x4(r0, r1, r2, r3, kb + ((p*16 + lmr) * 72 + kk*16 + lmk) * 2);
                unsigned b0[2] = { r0, r2 }, b1[2] = { r1, r3 };
                mma16h(sacc[2*p],   qa[kk], b0);
                mma16h(sacc[2*p+1], qa[kk], b1);
            }
        }

        bool nomask = (s0 + 63 <= warp_tmin) && (s0 + 64 <= SS);
        if (nomask) {
            #pragma unroll
            for (int nt = 0; nt < 8; nt++)
                #pragma unroll
                for (int i = 0; i < 4; i++) sacc[nt][i] *= 0.125f;
        } else {
            #pragma unroll
            for (int nt = 0; nt < 8; nt++) {
                int j = s0 + nt*8 + q*2;
                sacc[nt][0] = (j     <= t_r0 && j     < SS) ? sacc[nt][0]*0.125f : -1e30f;
                sacc[nt][1] = (j + 1 <= t_r0 && j + 1 < SS) ? sacc[nt][1]*0.125f : -1e30f;
                sacc[nt][2] = (j     <= t_r1 && j     < SS) ? sacc[nt][2]*0.125f : -1e30f;
                sacc[nt][3] = (j + 1 <= t_r1 && j + 1 < SS) ? sacc[nt][3]*0.125f : -1e30f;
            }
        }

        float mx0 = -1e30f, mx1 = -1e30f;
        #pragma unroll
        for (int nt = 0; nt < 8; nt++) {
            mx0 = fmaxf(mx0, fmaxf(sacc[nt][0], sacc[nt][1]));
            mx1 = fmaxf(mx1, fmaxf(sacc[nt][2], sacc[nt][3]));
        }
        mx0 = fmaxf(mx0, __shfl_xor_sync(0xffffffffu, mx0, 1));
        mx0 = fmaxf(mx0, __shfl_xor_sync(0xffffffffu, mx0, 2));
        mx1 = fmaxf(mx1, __shfl_xor_sync(0xffffffffu, mx1, 1));
        mx1 = fmaxf(mx1, __shfl_xor_sync(0xffffffffu, mx1, 2));
        float mn0 = fmaxf(m0, mx0), mn1 = fmaxf(m1, mx1);
        float al0 = __expf(m0 - mn0), al1 = __expf(m1 - mn1);
        float rs0 = 0.f, rs1 = 0.f;
        #pragma unroll
        for (int nt = 0; nt < 8; nt++) {
            float p0 = __expf(sacc[nt][0] - mn0); sacc[nt][0] = p0; rs0 += p0;
            float p1 = __expf(sacc[nt][1] - mn0); sacc[nt][1] = p1; rs0 += p1;
            float p2 = __expf(sacc[nt][2] - mn1); sacc[nt][2] = p2; rs1 += p2;
            float p3 = __expf(sacc[nt][3] - mn1); sacc[nt][3] = p3; rs1 += p3;
        }
        rs0 += __shfl_xor_sync(0xffffffffu, rs0, 1);
        rs0 += __shfl_xor_sync(0xffffffffu, rs0, 2);
        rs1 += __shfl_xor_sync(0xffffffffu, rs1, 1);
        rs1 += __shfl_xor_sync(0xffffffffu, rs1, 2);
        l0 = l0 * al0 + rs0;
        l1 = l1 * al1 + rs1;
        m0 = mn0; m1 = mn1;
        #pragma unroll
        for (int nt = 0; nt < 8; nt++) {
            oacc[nt][0] *= al0; oacc[nt][1] *= al0;
            oacc[nt][2] *= al1; oacc[nt][3] *= al1;
        }

        // O += P @ V
        #pragma unroll
        for (int kt = 0; kt < 4; kt++) {
            unsigned pa[4];
            pa[0] = packh2(sacc[2*kt][0],     sacc[2*kt][1]);
            pa[1] = packh2(sacc[2*kt][2],     sacc[2*kt][3]);
            pa[2] = packh2(sacc[2*kt + 1][0], sacc[2*kt + 1][1]);
            pa[3] = packh2(sacc[2*kt + 1][2], sacc[2*kt + 1][3]);
            #pragma unroll
            for (int p = 0; p < 4; p++) {
                unsigned r0, r1, r2, r3;
                ldm_x4(r0, r1, r2, r3, vb + ((p*16 + lmr) * 72 + kt*16 + lmk) * 2);
                unsigned b0[2] = { r0, r2 }, b1[2] = { r1, r3 };
                mma16h(oacc[2*p],   pa, b0);
                mma16h(oacc[2*p+1], pa, b1);
            }
        }
    }

    float inv0 = 1.f / l0, inv1 = 1.f / l1;
    size_t r0 = ((size_t)b * Tt + t_r0) * DM + h * DH;
    size_t r1 = ((size_t)b * Tt + t_r1) * DM + h * DH;
    #pragma unroll
    for (int nt = 0; nt < 8; nt++) {
        int d = nt*8 + q*2;
        g_ctxh[r0 + d]     = __float2half_rn(oacc[nt][0] * inv0);
        g_ctxh[r0 + d + 1] = __float2half_rn(oacc[nt][1] * inv0);
        g_ctxh[r1 + d]     = __float2half_rn(oacc[nt][2] * inv1);
        g_ctxh[r1 + d + 1] = __float2half_rn(oacc[nt][3] * inv1);
    }
}

// ---------------- launch -------------------------------------------------------------------
extern "C" void kernel_launch(void* const* d_in, const int* in_sizes, int n_in,
                              void* d_out, int out_size) {
    const float* x  = (const float*)d_in[0];
    const float* wq = (const float*)d_in[1];
    const float* wk = (const float*)d_in[2];
    const float* wv = (const float*)d_in[3];
    const float* wp = (const float*)d_in[4];
    float* out = (float*)d_out;

    k_rtab   <<<(Tt * 32) / 256, 256>>>();
    k_split_x <<<(size_t)(Bb*Tt*DM) / 1024, 256>>>((const float4*)x);
    k_gatherc <<<(size_t)(Bb*SS*DM/4) / 256, 256>>>(x);
    k_split_wq<<<(size_t)(DM*DM)  / 1024, 256>>>((const float4*)wq);
    k_split_wk<<<(size_t)(512*DM) / 1024, 256>>>((const float4*)wk);
    k_split_wv<<<(size_t)(512*DM) / 1024, 256>>>((const float4*)wv);
    k_split_wp<<<(size_t)(DM*DM)  / 1024, 256>>>((const float4*)wp);

    k_gemm_q <<<dim3(DM / 128, (Bb * Tt) / 128), 256>>>();
    k_gemm_kv<<<dim3(1024 / 128, (Bb * SS + 127) / 128), 256>>>();

    k_rope_q<<<(Bb * Tt * NH * 32) / 256, 256>>>();
    k_rope_k<<<(Bb * SS * NKV * 32) / 256, 256>>>();
    k_perm_v<<<Bb * NKV * DH, 256>>>();

    k_flash<<<dim3(Tt / 128, Bb * NH), 256>>>();

    k_proj<<<dim3(DM / 128, (Bb * Tt) / 128), 256>>>(out);
}

// round 11
// speedup vs baseline: 12.7704x; 1.0171x over previous
#include <cuda_runtime.h>
#include <cuda_fp16.h>
#include <math.h>

#define Bb 2
#define Tt 4096
#define DM 2048
#define NH 32
#define NKV 8
#define DH 64
#define SS 1028
#define SINKN 4
#define POS_SHIFT 3068
#define VSP 1088

// ---------------- scratch (16B-aligned) --------------------------------------------
__device__ __align__(16) __half g_xh  [(size_t)Bb*Tt*DM];
__device__ __align__(16) __half g_wqh [(size_t)DM*DM];
__device__ __align__(16) __half g_wkvh[(size_t)1024*DM];
__device__ __align__(16) __half g_wph [(size_t)DM*DM];
__device__ __align__(16) __half g_ctxh[(size_t)Bb*Tt*DM];
__device__ __align__(16) __half g_Qh [(size_t)Bb*NH*Tt*DH];
__device__ __align__(16) __half g_Kh [(size_t)Bb*NKV*SS*DH];
__device__ __align__(16) __half g_vtm[(size_t)Bb*SS*512];
__device__ __align__(16) __half g_Vt [(size_t)Bb*NKV*DH*VSP];
__device__ __align__(16) float2 g_rtab[(size_t)Tt*32];

// ---------------- helpers ------------------------------------------------------------
__device__ __forceinline__ void mma16h(float c[4], const unsigned a[4], const unsigned b[2]) {
    asm volatile("mma.sync.aligned.m16n8k16.row.col.f32.f16.f16.f32 "
        "{%0,%1,%2,%3},{%4,%5,%6,%7},{%8,%9},{%0,%1,%2,%3};"
        : "+f"(c[0]), "+f"(c[1]), "+f"(c[2]), "+f"(c[3])
        : "r"(a[0]), "r"(a[1]), "r"(a[2]), "r"(a[3]), "r"(b[0]), "r"(b[1]));
}
__device__ __forceinline__ void ldm_x4(unsigned &r0, unsigned &r1, unsigned &r2, unsigned &r3,
                                       unsigned addr) {
    asm volatile("ldmatrix.sync.aligned.m8n8.x4.shared.b16 {%0,%1,%2,%3}, [%4];"
        : "=r"(r0), "=r"(r1), "=r"(r2), "=r"(r3) : "r"(addr));
}
__device__ __forceinline__ unsigned packh2(float lo, float hi) {
    __half2 h = __floats2half2_rn(lo, hi);
    return *reinterpret_cast<unsigned*>(&h);
}
__device__ __forceinline__ unsigned smem_u32(const void* p) {
    return (unsigned)__cvta_generic_to_shared(p);
}
__device__ __forceinline__ void cpa16(unsigned dst, const void* src) {
    asm volatile("cp.async.cg.shared.global [%0], [%1], 16;" :: "r"(dst), "l"(src));
}
__device__ __forceinline__ uint2 pack4(float4 v) {
    __half2 h0 = __floats2half2_rn(v.x, v.y);
    __half2 h1 = __floats2half2_rn(v.z, v.w);
    return make_uint2(*reinterpret_cast<unsigned*>(&h0), *reinterpret_cast<unsigned*>(&h1));
}

// ---------------- RoPE trig table ------------------------------------------------------
__global__ void k_rtab() {
    int idx = blockIdx.x * 256 + threadIdx.x;
    int i = idx & 31, t = idx >> 5;
    double inv = pow(10000.0, -(double)i / 32.0);
    double ang = (double)t * inv;
    g_rtab[idx] = make_float2((float)cos(ang), (float)sin(ang));
}

// ---------------- split kernels (x4 vectorized; dests named in device code) -------------
__global__ void k_split_x(const float4* __restrict__ s) {
    size_t i = (size_t)blockIdx.x * blockDim.x + threadIdx.x;
    *(uint2*)&g_xh[i * 4] = pack4(s[i]);
}
__global__ void k_split_wq(const float4* __restrict__ s) {
    size_t i = (size_t)blockIdx.x * blockDim.x + threadIdx.x;
    *(uint2*)&g_wqh[i * 4] = pack4(s[i]);
}
__global__ void k_split_wk(const float4* __restrict__ s) {
    size_t i = (size_t)blockIdx.x * blockDim.x + threadIdx.x;
    *(uint2*)&g_wkvh[i * 4] = pack4(s[i]);
}
__global__ void k_split_wv(const float4* __restrict__ s) {
    size_t i = (size_t)blockIdx.x * blockDim.x + threadIdx.x;
    *(uint2*)&g_wkvh[(size_t)512*DM + i * 4] = pack4(s[i]);
}
__global__ void k_split_wp(const float4* __restrict__ s) {
    size_t i = (size_t)blockIdx.x * blockDim.x + threadIdx.x;
    *(uint2*)&g_wph[i * 4] = pack4(s[i]);
}

// ---------------- fused fp16 GEMM (A/W selected in DEVICE code via MODE) -----------------
// MODE 0: g_xh @ g_wqh^T   -> rope -> g_Qh
// MODE 1: gather(g_xh) @ g_wkvh^T -> rope K -> g_Kh ; V -> g_vtm
// MODE 2: g_ctxh @ g_wph^T -> fp32 d_out
#define SK2  24

template<int MODE>
__global__ void __launch_bounds__(256, 2) k_gemm(float* __restrict__ C,
                                                 int M, int N, int K)
{
    const __half* A_ = (MODE == 2) ? g_ctxh : g_xh;
    const __half* W_ = (MODE == 0) ? g_wqh : (MODE == 1) ? g_wkvh : g_wph;

    __shared__ __align__(16) __half sm[3][2][128 * SK2];
    int tid = threadIdx.x, lane = tid & 31, wid = tid >> 5;
    int wm = wid >> 1, wn = wid & 1, gp = lane >> 2, q = lane & 3;
    int bm = blockIdx.y * 128, bn = blockIdx.x * 128;
    int lmr = lane & 15, lmk = (lane >> 4) * 8;

    float acc[2][8][4];
    #pragma unroll
    for (int mt = 0; mt < 2; mt++)
        #pragma unroll
        for (int nt = 0; nt < 8; nt++)
            #pragma unroll
            for (int i = 0; i < 4; i++) acc[mt][nt][i] = 0.f;

    int lr = tid >> 1, lseg = (tid & 1) * 8;
    int arow = bm + lr; if (arow > M - 1) arow = M - 1;
    int brow = bn + lr; if (brow > N - 1) brow = N - 1;
    const __half* ga;
    if (MODE == 1) {
        int ab = arow / SS, aj = arow % SS;
        int pos = (aj < SINKN) ? aj : aj + POS_SHIFT;
        ga = A_ + ((size_t)ab * Tt + pos) * DM + lseg;
    } else {
        ga = A_ + (size_t)arow * K + lseg;
    }
    const __half* gb = W_ + (size_t)brow * K + lseg;
    unsigned sda[3], sdb[3];
    #pragma unroll
    for (int s = 0; s < 3; s++) {
        sda[s] = smem_u32(&sm[s][0][lr * SK2 + lseg]);
        sdb[s] = smem_u32(&sm[s][1][lr * SK2 + lseg]);
    }

    int iters = K / 16;
    cpa16(sda[0], ga);      cpa16(sdb[0], gb);
    asm volatile("cp.async.commit_group;");
    cpa16(sda[1], ga + 16); cpa16(sdb[1], gb + 16);
    asm volatile("cp.async.commit_group;");

    for (int i = 0; i < iters; i++) {
        if (i == iters - 1) asm volatile("cp.async.wait_group 0;");
        else                asm volatile("cp.async.wait_group 1;");
        __syncthreads();

        if (i + 2 < iters) {
            int s = (i + 2) % 3, k0 = (i + 2) * 16;
            cpa16(sda[s], ga + k0);
            cpa16(sdb[s], gb + k0);
            asm volatile("cp.async.commit_group;");
        }

        int cur = i % 3;
        unsigned abase = smem_u32(&sm[cur][0][0]);
        unsigned bbase = smem_u32(&sm[cur][1][0]);

        unsigned a[2][4];
        #pragma unroll
        for (int mt = 0; mt < 2; mt++)
            ldm_x4(a[mt][0], a[mt][1], a[mt][2], a[mt][3],
                   abase + ((wm*32 + mt*16 + lmr) * SK2 + lmk) * 2);

        #pragma unroll
        for (int p = 0; p < 4; p++) {
            unsigned r0, r1, r2, r3;
            ldm_x4(r0, r1, r2, r3, bbase + ((wn*64 + p*16 + lmr) * SK2 + lmk) * 2);
            unsigned b0[2] = { r0, r2 }, b1[2] = { r1, r3 };
            mma16h(acc[0][2*p],   a[0], b0);
            mma16h(acc[1][2*p],   a[1], b0);
            mma16h(acc[0][2*p+1], a[0], b1);
            mma16h(acc[1][2*p+1], a[1], b1);
        }
    }

    // ---------------- epilogues ----------------
    int cb = bn + wn * 64;           // warp column base (one 64-wide head)
    if (MODE == 0) {
        int h = cb >> 6;
        #pragma unroll
        for (int mt = 0; mt < 2; mt++) {
            int r = bm + wm * 32 + mt * 16 + gp;
            #pragma unroll
            for (int half_ = 0; half_ < 2; half_++) {
                int rr = r + half_ * 8;
                int b = rr >> 12, t = rr & 4095;
                size_t o = (((size_t)b * NH + h) * Tt + t) * DH;
                #pragma unroll
                for (int nt = 0; nt < 4; nt++) {
                    int i2 = nt * 8 + q * 2;
                    float x1a = acc[mt][nt][2*half_],     x1b = acc[mt][nt][2*half_ + 1];
                    float x2a = acc[mt][nt + 4][2*half_], x2b = acc[mt][nt + 4][2*half_ + 1];
                    float2 ca  = g_rtab[t * 32 + i2];
                    float2 cbv = g_rtab[t * 32 + i2 + 1];
                    *(unsigned*)&g_Qh[o + i2] =
                        packh2(x1a * ca.x - x2a * ca.y, x1b * cbv.x - x2b * cbv.y);
                    *(unsigned*)&g_Qh[o + i2 + 32] =
                        packh2(x2a * ca.x + x1a * ca.y, x2b * cbv.x + x1b * cbv.y);
                }
            }
        }
    } else if (MODE == 1) {
        int hb = cb >> 6;            // 0..7 = K heads, 8..15 = V heads
        #pragma unroll
        for (int mt = 0; mt < 2; mt++) {
            int r = bm + wm * 32 + mt * 16 + gp;
            #pragma unroll
            for (int half_ = 0; half_ < 2; half_++) {
                int rr = r + half_ * 8;
                if (rr >= M) continue;
                int b = (rr >= SS) ? 1 : 0;
                int j = rr - b * SS;
                if (hb < 8) {
                    int pos = (j < SINKN) ? j : j + POS_SHIFT;
                    size_t o = (((size_t)b * NKV + hb) * SS + j) * DH;
                    #pragma unroll
                    for (int nt = 0; nt < 4; nt++) {
                        int i2 = nt * 8 + q * 2;
                        float x1a = acc[mt][nt][2*half_],     x1b = acc[mt][nt][2*half_ + 1];
                        float x2a = acc[mt][nt + 4][2*half_], x2b = acc[mt][nt + 4][2*half_ + 1];
                        float2 ca  = g_rtab[pos * 32 + i2];
                        float2 cbv = g_rtab[pos * 32 + i2 + 1];
                        *(unsigned*)&g_Kh[o + i2] =
                            packh2(x1a * ca.x - x2a * ca.y, x1b * cbv.x - x2b * cbv.y);
                        *(unsigned*)&g_Kh[o + i2 + 32] =
                            packh2(x2a * ca.x + x1a * ca.y, x2b * cbv.x + x1b * cbv.y);
                    }
                } else {
                    size_t o = ((size_t)b * SS + j) * 512 + (hb - 8) * 64;
                    #pragma unroll
                    for (int nt = 0; nt < 8; nt++) {
                        int d = nt * 8 + q * 2;
                        *(unsigned*)&g_vtm[o + d] =
                            packh2(acc[mt][nt][2*half_], acc[mt][nt][2*half_ + 1]);
                    }
                }
            }
        }
    } else {
        #pragma unroll
        for (int mt = 0; mt < 2; mt++) {
            int r = bm + wm * 32 + mt * 16 + gp;
            #pragma unroll
            for (int nt = 0; nt < 8; nt++) {
                int cc = cb + nt * 8 + q * 2;
                C[(size_t)r * N + cc]       = acc[mt][nt][0];
                C[(size_t)r * N + cc + 1]   = acc[mt][nt][1];
                C[(size_t)(r+8) * N + cc]   = acc[mt][nt][2];
                C[(size_t)(r+8) * N + cc+1] = acc[mt][nt][3];
            }
        }
    }
}

// ---------------- V permute (fp16 -> transposed padded) ----------------------------------
__global__ void k_perm_v() {
    int bkd = blockIdx.x;
    int d  = bkd & 63;
    int bk = bkd >> 6;
    int b  = bk >> 3, kh = bk & 7;
    for (int s = threadIdx.x; s < VSP; s += 256) {
        __half v = __float2half(0.f);
        if (s < SS) v = g_vtm[((size_t)b * SS + s) * 512 + kh * 64 + d];
        g_Vt[((size_t)bk * DH + d) * VSP + s] = v;
    }
}

// ---------------- fused flash attention (fp16 mma16 + ldmatrix) ---------------------------
__global__ void __launch_bounds__(256, 2) k_flash() {
    __shared__ __align__(16) __half Ks [64 * 72];
    __shared__ __align__(16) __half Vts[64 * 72];
    int tid = threadIdx.x, lane = tid & 31, wid = tid >> 5;
    int gp = lane >> 2, q = lane & 3;
    int lmr = lane & 15, lmk = (lane >> 4) * 8;
    int t0 = blockIdx.x * 128;
    int z = blockIdx.y;
    int b = z >> 5, h = z & 31, kvh = h >> 2;
    int bk = b * NKV + kvh;
    const __half* Qp = g_Qh + (size_t)z * Tt * DH;
    const __half* Kp = g_Kh + (size_t)bk * SS * DH;
    const __half* Vp = g_Vt + (size_t)bk * DH * VSP;

    int t_r0 = t0 + wid * 16 + gp;
    int t_r1 = t_r0 + 8;
    int warp_tmin = t0 + wid * 16;
    int s_end = min(SS, t0 + 128);

    unsigned qa[4][4];
    {
        const unsigned* uQ0 = (const unsigned*)(Qp + (size_t)t_r0 * DH);
        const unsigned* uQ1 = (const unsigned*)(Qp + (size_t)t_r1 * DH);
        #pragma unroll
        for (int kk = 0; kk < 4; kk++) {
            qa[kk][0] = uQ0[kk * 8 + q];
            qa[kk][1] = uQ1[kk * 8 + q];
            qa[kk][2] = uQ0[kk * 8 + q + 4];
            qa[kk][3] = uQ1[kk * 8 + q + 4];
        }
    }

    float oacc[8][4];
    #pragma unroll
    for (int nt = 0; nt < 8; nt++)
        #pragma unroll
        for (int i = 0; i < 4; i++) oacc[nt][i] = 0.f;
    float m0 = -1e30f, m1 = -1e30f, l0 = 0.f, l1 = 0.f;

    unsigned kb = smem_u32(Ks);
    unsigned vb = smem_u32(Vts);

    for (int s0 = 0; s0 < s_end; s0 += 64) {
        __syncthreads();
        #pragma unroll
        for (int i = 0; i < 2; i++) {
            int f = i * 256 + tid;
            int r = f >> 3, sg = (f & 7) * 8;
            uint4 kv = make_uint4(0, 0, 0, 0);
            int srow = s0 + r;
            if (srow < SS) kv = *(const uint4*)(Kp + (size_t)srow * DH + sg);
            *(uint4*)(&Ks[r * 72 + sg]) = kv;
            uint4 vv = *(const uint4*)(Vp + (size_t)r * VSP + s0 + sg);
            *(uint4*)(&Vts[r * 72 + sg]) = vv;
        }
        __syncthreads();

        float sacc[8][4];
        #pragma unroll
        for (int nt = 0; nt < 8; nt++)
            #pragma unroll
            for (int i = 0; i < 4; i++) sacc[nt][i] = 0.f;
        #pragma unroll
        for (int kk = 0; kk < 4; kk++) {
            #pragma unroll
            for (int p = 0; p < 4; p++) {
                unsigned r0, r1, r2, r3;
                ldm_x4(r0, r1, r2, r3, kb + ((p*16 + lmr) * 72 + kk*16 + lmk) * 2);
                unsigned b0[2] = { r0, r2 }, b1[2] = { r1, r3 };
                mma16h(sacc[2*p],   qa[kk], b0);
                mma16h(sacc[2*p+1], qa[kk], b1);
            }
        }

        bool nomask = (s0 + 63 <= warp_tmin) && (s0 + 64 <= SS);
        if (nomask) {
            #pragma unroll
            for (int nt = 0; nt < 8; nt++)
                #pragma unroll
                for (int i = 0; i < 4; i++) sacc[nt][i] *= 0.125f;
        } else {
            #pragma unroll
            for (int nt = 0; nt < 8; nt++) {
                int j = s0 + nt*8 + q*2;
                sacc[nt][0] = (j     <= t_r0 && j     < SS) ? sacc[nt][0]*0.125f : -1e30f;
                sacc[nt][1] = (j + 1 <= t_r0 && j + 1 < SS) ? sacc[nt][1]*0.125f : -1e30f;
                sacc[nt][2] = (j     <= t_r1 && j     < SS) ? sacc[nt][2]*0.125f : -1e30f;
                sacc[nt][3] = (j + 1 <= t_r1 && j + 1 < SS) ? sacc[nt][3]*0.125f : -1e30f;
            }
        }

        float mx0 = -1e30f, mx1 = -1e30f;
        #pragma unroll
        for (int nt = 0; nt < 8; nt++) {
            mx0 = fmaxf(mx0, fmaxf(sacc[nt][0], sacc[nt][1]));
            mx1 = fmaxf(mx1, fmaxf(sacc[nt][2], sacc[nt][3]));
        }
        mx0 = fmaxf(mx0, __shfl_xor_sync(0xffffffffu, mx0, 1));
        mx0 = fmaxf(mx0, __shfl_xor_sync(0xffffffffu, mx0, 2));
        mx1 = fmaxf(mx1, __shfl_xor_sync(0xffffffffu, mx1, 1));
        mx1 = fmaxf(mx1, __shfl_xor_sync(0xffffffffu, mx1, 2));
        float mn0 = fmaxf(m0, mx0), mn1 = fmaxf(m1, mx1);
        float al0 = __expf(m0 - mn0), al1 = __expf(m1 - mn1);
        float rs0 = 0.f, rs1 = 0.f;
        #pragma unroll
        for (int nt = 0; nt < 8; nt++) {
            float p0 = __expf(sacc[nt][0] - mn0); sacc[nt][0] = p0; rs0 += p0;
            float p1 = __expf(sacc[nt][1] - mn0); sacc[nt][1] = p1; rs0 += p1;
            float p2 = __expf(sacc[nt][2] - mn1); sacc[nt][2] = p2; rs1 += p2;
            float p3 = __expf(sacc[nt][3] - mn1); sacc[nt][3] = p3; rs1 += p3;
        }
        rs0 += __shfl_xor_sync(0xffffffffu, rs0, 1);
        rs0 += __shfl_xor_sync(0xffffffffu, rs0, 2);
        rs1 += __shfl_xor_sync(0xffffffffu, rs1, 1);
        rs1 += __shfl_xor_sync(0xffffffffu, rs1, 2);
        l0 = l0 * al0 + rs0;
        l1 = l1 * al1 + rs1;
        m0 = mn0; m1 = mn1;
        #pragma unroll
        for (int nt = 0; nt < 8; nt++) {
            oacc[nt][0] *= al0; oacc[nt][1] *= al0;
            oacc[nt][2] *= al1; oacc[nt][3] *= al1;
        }

        #pragma unroll
        for (int kt = 0; kt < 4; kt++) {
            unsigned pa[4];
            pa[0] = packh2(sacc[2*kt][0],     sacc[2*kt][1]);
            pa[1] = packh2(sacc[2*kt][2],     sacc[2*kt][3]);
            pa[2] = packh2(sacc[2*kt + 1][0], sacc[2*kt + 1][1]);
            pa[3] = packh2(sacc[2*kt + 1][2], sacc[2*kt + 1][3]);
            #pragma unroll
            for (int p = 0; p < 4; p++) {
                unsigned r0, r1, r2, r3;
                ldm_x4(r0, r1, r2, r3, vb + ((p*16 + lmr) * 72 + kt*16 + lmk) * 2);
                unsigned b0[2] = { r0, r2 }, b1[2] = { r1, r3 };
                mma16h(oacc[2*p],   pa, b0);
                mma16h(oacc[2*p+1], pa, b1);
            }
        }
    }

    float inv0 = 1.f / l0, inv1 = 1.f / l1;
    size_t r0 = ((size_t)b * Tt + t_r0) * DM + h * DH;
    size_t r1 = ((size_t)b * Tt + t_r1) * DM + h * DH;
    #pragma unroll
    for (int nt = 0; nt < 8; nt++) {
        int d = nt*8 + q*2;
        g_ctxh[r0 + d]     = __float2half_rn(oacc[nt][0] * inv0);
        g_ctxh[r0 + d + 1] = __float2half_rn(oacc[nt][1] * inv0);
        g_ctxh[r1 + d]     = __float2half_rn(oacc[nt][2] * inv1);
        g_ctxh[r1 + d + 1] = __float2half_rn(oacc[nt][3] * inv1);
    }
}

// ---------------- launch -------------------------------------------------------------------
extern "C" void kernel_launch(void* const* d_in, const int* in_sizes, int n_in,
                              void* d_out, int out_size) {
    const float* x  = (const float*)d_in[0];
    const float* wq = (const float*)d_in[1];
    const float* wk = (const float*)d_in[2];
    const float* wv = (const float*)d_in[3];
    const float* wp = (const float*)d_in[4];
    float* out = (float*)d_out;

    k_rtab    <<<(Tt * 32) / 256, 256>>>();
    k_split_x <<<(size_t)(Bb*Tt*DM) / 1024, 256>>>((const float4*)x);
    k_split_wq<<<(size_t)(DM*DM)  / 1024, 256>>>((const float4*)wq);
    k_split_wk<<<(size_t)(512*DM) / 1024, 256>>>((const float4*)wk);
    k_split_wv<<<(size_t)(512*DM) / 1024, 256>>>((const float4*)wv);
    k_split_wp<<<(size_t)(DM*DM)  / 1024, 256>>>((const float4*)wp);

    k_gemm<0><<<dim3(DM / 128, (Bb * Tt) / 128), 256>>>(nullptr, Bb*Tt, DM, DM);
    k_gemm<1><<<dim3(1024 / 128, (Bb * SS + 127) / 128), 256>>>(nullptr, Bb*SS, 1024, DM);

    k_perm_v<<<Bb * NKV * DH, 256>>>();

    k_flash<<<dim3(Tt / 128, Bb * NH), 256>>>();

    k_gemm<2><<<dim3(DM / 128, (Bb * Tt) / 128), 256>>>(out, Bb*Tt, DM, DM);
}

// round 12
// speedup vs baseline: 13.2126x; 1.0346x over previous
#include <cuda_runtime.h>
#include <cuda_fp16.h>
#include <math.h>

#define Bb 2
#define Tt 4096
#define DM 2048
#define NH 32
#define NKV 8
#define DH 64
#define SS 1028
#define SINKN 4
#define POS_SHIFT 3068

// ---------------- scratch (16B-aligned) --------------------------------------------
__device__ __align__(16) __half g_xh  [(size_t)Bb*Tt*DM];
__device__ __align__(16) __half g_wqh [(size_t)DM*DM];
__device__ __align__(16) __half g_wkvh[(size_t)1024*DM];
__device__ __align__(16) __half g_wph [(size_t)DM*DM];
__device__ __align__(16) __half g_ctxh[(size_t)Bb*Tt*DM];
__device__ __align__(16) __half g_Qh [(size_t)Bb*NH*Tt*DH];
__device__ __align__(16) __half g_Kh [(size_t)Bb*NKV*SS*DH];
__device__ __align__(16) __half g_vtm[(size_t)Bb*SS*512];
__device__ __align__(16) float2 g_rtab[(size_t)Tt*32];

// ---------------- helpers ------------------------------------------------------------
__device__ __forceinline__ void mma16h(float c[4], const unsigned a[4], const unsigned b[2]) {
    asm volatile("mma.sync.aligned.m16n8k16.row.col.f32.f16.f16.f32 "
        "{%0,%1,%2,%3},{%4,%5,%6,%7},{%8,%9},{%0,%1,%2,%3};"
        : "+f"(c[0]), "+f"(c[1]), "+f"(c[2]), "+f"(c[3])
        : "r"(a[0]), "r"(a[1]), "r"(a[2]), "r"(a[3]), "r"(b[0]), "r"(b[1]));
}
__device__ __forceinline__ void ldm_x4(unsigned &r0, unsigned &r1, unsigned &r2, unsigned &r3,
                                       unsigned addr) {
    asm volatile("ldmatrix.sync.aligned.m8n8.x4.shared.b16 {%0,%1,%2,%3}, [%4];"
        : "=r"(r0), "=r"(r1), "=r"(r2), "=r"(r3) : "r"(addr));
}
__device__ __forceinline__ void ldm_x4_t(unsigned &r0, unsigned &r1, unsigned &r2, unsigned &r3,
                                         unsigned addr) {
    asm volatile("ldmatrix.sync.aligned.m8n8.x4.trans.shared.b16 {%0,%1,%2,%3}, [%4];"
        : "=r"(r0), "=r"(r1), "=r"(r2), "=r"(r3) : "r"(addr));
}
__device__ __forceinline__ unsigned packh2(float lo, float hi) {
    __half2 h = __floats2half2_rn(lo, hi);
    return *reinterpret_cast<unsigned*>(&h);
}
__device__ __forceinline__ unsigned smem_u32(const void* p) {
    return (unsigned)__cvta_generic_to_shared(p);
}
__device__ __forceinline__ void cpa16(unsigned dst, const void* src) {
    asm volatile("cp.async.cg.shared.global [%0], [%1], 16;" :: "r"(dst), "l"(src));
}
__device__ __forceinline__ void cpa16z(unsigned dst, const void* src, unsigned sz) {
    asm volatile("cp.async.cg.shared.global [%0], [%1], 16, %2;" :: "r"(dst), "l"(src), "r"(sz));
}
__device__ __forceinline__ uint2 pack4(float4 v) {
    __half2 h0 = __floats2half2_rn(v.x, v.y);
    __half2 h1 = __floats2half2_rn(v.z, v.w);
    return make_uint2(*reinterpret_cast<unsigned*>(&h0), *reinterpret_cast<unsigned*>(&h1));
}

// ---------------- RoPE trig table ------------------------------------------------------
__global__ void k_rtab() {
    int idx = blockIdx.x * 256 + threadIdx.x;
    int i = idx & 31, t = idx >> 5;
    double inv = pow(10000.0, -(double)i / 32.0);
    double ang = (double)t * inv;
    g_rtab[idx] = make_float2((float)cos(ang), (float)sin(ang));
}

// ---------------- split kernels (dests named in device code) ----------------------------
__global__ void k_split_x(const float4* __restrict__ s) {
    size_t i = (size_t)blockIdx.x * blockDim.x + threadIdx.x;
    *(uint2*)&g_xh[i * 4] = pack4(s[i]);
}
__global__ void k_split_w(const float4* __restrict__ wq, const float4* __restrict__ wk,
                          const float4* __restrict__ wv, const float4* __restrict__ wp) {
    size_t i = (size_t)blockIdx.x * 256 + threadIdx.x;
    const size_t NQ = (size_t)DM * DM / 4;       // 1048576
    const size_t NK = (size_t)512 * DM / 4;      // 262144
    if (i < NQ) {
        *(uint2*)&g_wqh[i * 4] = pack4(wq[i]);
    } else if (i < NQ + NK) {
        size_t j = i - NQ;
        *(uint2*)&g_wkvh[j * 4] = pack4(wk[j]);
    } else if (i < NQ + 2 * NK) {
        size_t j = i - NQ - NK;
        *(uint2*)&g_wkvh[(size_t)512 * DM + j * 4] = pack4(wv[j]);
    } else {
        size_t j = i - NQ - 2 * NK;
        *(uint2*)&g_wph[j * 4] = pack4(wp[j]);
    }
}

// ---------------- fused fp16 GEMM (A/W selected in DEVICE code via MODE) -----------------
// MODE 0: g_xh @ g_wqh^T   -> rope * 0.125 -> g_Qh
// MODE 1: gather(g_xh) @ g_wkvh^T -> rope K -> g_Kh ; V -> g_vtm
// MODE 2: g_ctxh @ g_wph^T -> fp32 d_out
#define SK2  24

template<int MODE>
__global__ void __launch_bounds__(256, 2) k_gemm(float* __restrict__ C,
                                                 int M, int N, int K)
{
    const __half* A_ = (MODE == 2) ? g_ctxh : g_xh;
    const __half* W_ = (MODE == 0) ? g_wqh : (MODE == 1) ? g_wkvh : g_wph;

    __shared__ __align__(16) __half sm[3][2][128 * SK2];
    int tid = threadIdx.x, lane = tid & 31, wid = tid >> 5;
    int wm = wid >> 1, wn = wid & 1, gp = lane >> 2, q = lane & 3;
    int bm = blockIdx.y * 128, bn = blockIdx.x * 128;
    int lmr = lane & 15, lmk = (lane >> 4) * 8;

    float acc[2][8][4];
    #pragma unroll
    for (int mt = 0; mt < 2; mt++)
        #pragma unroll
        for (int nt = 0; nt < 8; nt++)
            #pragma unroll
            for (int i = 0; i < 4; i++) acc[mt][nt][i] = 0.f;

    int lr = tid >> 1, lseg = (tid & 1) * 8;
    int arow = bm + lr; if (arow > M - 1) arow = M - 1;
    int brow = bn + lr; if (brow > N - 1) brow = N - 1;
    const __half* ga;
    if (MODE == 1) {
        int ab = arow / SS, aj = arow % SS;
        int pos = (aj < SINKN) ? aj : aj + POS_SHIFT;
        ga = A_ + ((size_t)ab * Tt + pos) * DM + lseg;
    } else {
        ga = A_ + (size_t)arow * K + lseg;
    }
    const __half* gb = W_ + (size_t)brow * K + lseg;
    unsigned sda[3], sdb[3];
    #pragma unroll
    for (int s = 0; s < 3; s++) {
        sda[s] = smem_u32(&sm[s][0][lr * SK2 + lseg]);
        sdb[s] = smem_u32(&sm[s][1][lr * SK2 + lseg]);
    }

    int iters = K / 16;
    cpa16(sda[0], ga);      cpa16(sdb[0], gb);
    asm volatile("cp.async.commit_group;");
    cpa16(sda[1], ga + 16); cpa16(sdb[1], gb + 16);
    asm volatile("cp.async.commit_group;");

    for (int i = 0; i < iters; i++) {
        if (i == iters - 1) asm volatile("cp.async.wait_group 0;");
        else                asm volatile("cp.async.wait_group 1;");
        __syncthreads();

        if (i + 2 < iters) {
            int s = (i + 2) % 3, k0 = (i + 2) * 16;
            cpa16(sda[s], ga + k0);
            cpa16(sdb[s], gb + k0);
            asm volatile("cp.async.commit_group;");
        }

        int cur = i % 3;
        unsigned abase = smem_u32(&sm[cur][0][0]);
        unsigned bbase = smem_u32(&sm[cur][1][0]);

        unsigned a[2][4];
        #pragma unroll
        for (int mt = 0; mt < 2; mt++)
            ldm_x4(a[mt][0], a[mt][1], a[mt][2], a[mt][3],
                   abase + ((wm*32 + mt*16 + lmr) * SK2 + lmk) * 2);

        #pragma unroll
        for (int p = 0; p < 4; p++) {
            unsigned r0, r1, r2, r3;
            ldm_x4(r0, r1, r2, r3, bbase + ((wn*64 + p*16 + lmr) * SK2 + lmk) * 2);
            unsigned b0[2] = { r0, r2 }, b1[2] = { r1, r3 };
            mma16h(acc[0][2*p],   a[0], b0);
            mma16h(acc[1][2*p],   a[1], b0);
            mma16h(acc[0][2*p+1], a[0], b1);
            mma16h(acc[1][2*p+1], a[1], b1);
        }
    }

    // ---------------- epilogues ----------------
    int cb = bn + wn * 64;
    if (MODE == 0) {
        int h = cb >> 6;
        #pragma unroll
        for (int mt = 0; mt < 2; mt++) {
            int r = bm + wm * 32 + mt * 16 + gp;
            #pragma unroll
            for (int half_ = 0; half_ < 2; half_++) {
                int rr = r + half_ * 8;
                int b = rr >> 12, t = rr & 4095;
                size_t o = (((size_t)b * NH + h) * Tt + t) * DH;
                #pragma unroll
                for (int nt = 0; nt < 4; nt++) {
                    int i2 = nt * 8 + q * 2;
                    float x1a = acc[mt][nt][2*half_],     x1b = acc[mt][nt][2*half_ + 1];
                    float x2a = acc[mt][nt + 4][2*half_], x2b = acc[mt][nt + 4][2*half_ + 1];
                    float2 ca  = g_rtab[t * 32 + i2];
                    float2 cbv = g_rtab[t * 32 + i2 + 1];
                    *(unsigned*)&g_Qh[o + i2] =
                        packh2(0.125f * (x1a * ca.x - x2a * ca.y),
                               0.125f * (x1b * cbv.x - x2b * cbv.y));
                    *(unsigned*)&g_Qh[o + i2 + 32] =
                        packh2(0.125f * (x2a * ca.x + x1a * ca.y),
                               0.125f * (x2b * cbv.x + x1b * cbv.y));
                }
            }
        }
    } else if (MODE == 1) {
        int hb = cb >> 6;
        #pragma unroll
        for (int mt = 0; mt < 2; mt++) {
            int r = bm + wm * 32 + mt * 16 + gp;
            #pragma unroll
            for (int half_ = 0; half_ < 2; half_++) {
                int rr = r + half_ * 8;
                if (rr >= M) continue;
                int b = (rr >= SS) ? 1 : 0;
                int j = rr - b * SS;
                if (hb < 8) {
                    int pos = (j < SINKN) ? j : j + POS_SHIFT;
                    size_t o = (((size_t)b * NKV + hb) * SS + j) * DH;
                    #pragma unroll
                    for (int nt = 0; nt < 4; nt++) {
                        int i2 = nt * 8 + q * 2;
                        float x1a = acc[mt][nt][2*half_],     x1b = acc[mt][nt][2*half_ + 1];
                        float x2a = acc[mt][nt + 4][2*half_], x2b = acc[mt][nt + 4][2*half_ + 1];
                        float2 ca  = g_rtab[pos * 32 + i2];
                        float2 cbv = g_rtab[pos * 32 + i2 + 1];
                        *(unsigned*)&g_Kh[o + i2] =
                            packh2(x1a * ca.x - x2a * ca.y, x1b * cbv.x - x2b * cbv.y);
                        *(unsigned*)&g_Kh[o + i2 + 32] =
                            packh2(x2a * ca.x + x1a * ca.y, x2b * cbv.x + x1b * cbv.y);
                    }
                } else {
                    size_t o = ((size_t)b * SS + j) * 512 + (hb - 8) * 64;
                    #pragma unroll
                    for (int nt = 0; nt < 8; nt++) {
                        int d = nt * 8 + q * 2;
                        *(unsigned*)&g_vtm[o + d] =
                            packh2(acc[mt][nt][2*half_], acc[mt][nt][2*half_ + 1]);
                    }
                }
            }
        }
    } else {
        #pragma unroll
        for (int mt = 0; mt < 2; mt++) {
            int r = bm + wm * 32 + mt * 16 + gp;
            #pragma unroll
            for (int nt = 0; nt < 8; nt++) {
                int cc = cb + nt * 8 + q * 2;
                C[(size_t)r * N + cc]       = acc[mt][nt][0];
                C[(size_t)r * N + cc + 1]   = acc[mt][nt][1];
                C[(size_t)(r+8) * N + cc]   = acc[mt][nt][2];
                C[(size_t)(r+8) * N + cc+1] = acc[mt][nt][3];
            }
        }
    }
}

// ---------------- fused flash attention (double-buffered, V via ldmatrix.trans) -----------
__global__ void __launch_bounds__(256, 2) k_flash() {
    __shared__ __align__(16) __half Ks[2][64 * 72];
    __shared__ __align__(16) __half Vs[2][64 * 72];   // s-major: row=s, col=d
    int tid = threadIdx.x, lane = tid & 31, wid = tid >> 5;
    int gp = lane >> 2, q = lane & 3;
    int lmr = lane & 15, lmk = (lane >> 4) * 8;
    int t0 = blockIdx.x * 128;
    int z = blockIdx.y;
    int b = z >> 5, h = z & 31, kvh = h >> 2;
    int bk = b * NKV + kvh;
    const __half* Qp = g_Qh + (size_t)z * Tt * DH;
    const __half* Kp = g_Kh + (size_t)bk * SS * DH;
    const __half* Vp = g_vtm + (size_t)b * SS * 512 + kvh * 64;

    int t_r0 = t0 + wid * 16 + gp;
    int t_r1 = t_r0 + 8;
    int warp_tmin = t0 + wid * 16;
    int s_end = min(SS, t0 + 128);
    int ntiles = (s_end + 63) >> 6;

    unsigned kbs[2] = { smem_u32(Ks[0]), smem_u32(Ks[1]) };
    unsigned vbs[2] = { smem_u32(Vs[0]), smem_u32(Vs[1]) };

    auto load_tile = [&](int s0, int st) {
        #pragma unroll
        for (int c = 0; c < 2; c++) {
            int f = c * 256 + tid;
            int r = f >> 3, sg = (f & 7) * 8;
            int srow = s0 + r;
            unsigned sz = (srow < SS) ? 16u : 0u;
            cpa16z(kbs[st] + (r * 72 + sg) * 2, Kp + (size_t)srow * DH + sg, sz);
            cpa16z(vbs[st] + (r * 72 + sg) * 2, Vp + (size_t)srow * 512 + sg, sz);
        }
        asm volatile("cp.async.commit_group;");
    };

    unsigned qa[4][4];
    {
        const unsigned* uQ0 = (const unsigned*)(Qp + (size_t)t_r0 * DH);
        const unsigned* uQ1 = (const unsigned*)(Qp + (size_t)t_r1 * DH);
        #pragma unroll
        for (int kk = 0; kk < 4; kk++) {
            qa[kk][0] = uQ0[kk * 8 + q];
            qa[kk][1] = uQ1[kk * 8 + q];
            qa[kk][2] = uQ0[kk * 8 + q + 4];
            qa[kk][3] = uQ1[kk * 8 + q + 4];
        }
    }

    float oacc[8][4];
    #pragma unroll
    for (int nt = 0; nt < 8; nt++)
        #pragma unroll
        for (int i = 0; i < 4; i++) oacc[nt][i] = 0.f;
    float m0 = -1e30f, m1 = -1e30f, l0 = 0.f, l1 = 0.f;

    load_tile(0, 0);

    for (int ti = 0; ti < ntiles; ti++) {
        int s0 = ti * 64;
        asm volatile("cp.async.wait_group 0;");
        __syncthreads();
        if (ti + 1 < ntiles) load_tile((ti + 1) * 64, (ti + 1) & 1);

        int st = ti & 1;
        unsigned kb = kbs[st], vb = vbs[st];

        // S = Q K^T (Q pre-scaled by 0.125)
        float sacc[8][4];
        #pragma unroll
        for (int nt = 0; nt < 8; nt++)
            #pragma unroll
            for (int i = 0; i < 4; i++) sacc[nt][i] = 0.f;
        #pragma unroll
        for (int kk = 0; kk < 4; kk++) {
            #pragma unroll
            for (int p = 0; p < 4; p++) {
                unsigned r0, r1, r2, r3;
                ldm_x4(r0, r1, r2, r3, kb + ((p*16 + lmr) * 72 + kk*16 + lmk) * 2);
                unsigned b0[2] = { r0, r2 }, b1[2] = { r1, r3 };
                mma16h(sacc[2*p],   qa[kk], b0);
                mma16h(sacc[2*p+1], qa[kk], b1);
            }
        }

        bool nomask = (s0 + 63 <= warp_tmin) && (s0 + 64 <= SS);
        if (!nomask) {
            #pragma unroll
            for (int nt = 0; nt < 8; nt++) {
                int j = s0 + nt*8 + q*2;
                if (!(j     <= t_r0 && j     < SS)) sacc[nt][0] = -1e30f;
                if (!(j + 1 <= t_r0 && j + 1 < SS)) sacc[nt][1] = -1e30f;
                if (!(j     <= t_r1 && j     < SS)) sacc[nt][2] = -1e30f;
                if (!(j + 1 <= t_r1 && j + 1 < SS)) sacc[nt][3] = -1e30f;
            }
        }

        float mx0 = -1e30f, mx1 = -1e30f;
        #pragma unroll
        for (int nt = 0; nt < 8; nt++) {
            mx0 = fmaxf(mx0, fmaxf(sacc[nt][0], sacc[nt][1]));
            mx1 = fmaxf(mx1, fmaxf(sacc[nt][2], sacc[nt][3]));
        }
        mx0 = fmaxf(mx0, __shfl_xor_sync(0xffffffffu, mx0, 1));
        mx0 = fmaxf(mx0, __shfl_xor_sync(0xffffffffu, mx0, 2));
        mx1 = fmaxf(mx1, __shfl_xor_sync(0xffffffffu, mx1, 1));
        mx1 = fmaxf(mx1, __shfl_xor_sync(0xffffffffu, mx1, 2));
        float mn0 = fmaxf(m0, mx0), mn1 = fmaxf(m1, mx1);
        float al0 = __expf(m0 - mn0), al1 = __expf(m1 - mn1);
        float rs0 = 0.f, rs1 = 0.f;
        #pragma unroll
        for (int nt = 0; nt < 8; nt++) {
            float p0 = __expf(sacc[nt][0] - mn0); sacc[nt][0] = p0; rs0 += p0;
            float p1 = __expf(sacc[nt][1] - mn0); sacc[nt][1] = p1; rs0 += p1;
            float p2 = __expf(sacc[nt][2] - mn1); sacc[nt][2] = p2; rs1 += p2;
            float p3 = __expf(sacc[nt][3] - mn1); sacc[nt][3] = p3; rs1 += p3;
        }
        rs0 += __shfl_xor_sync(0xffffffffu, rs0, 1);
        rs0 += __shfl_xor_sync(0xffffffffu, rs0, 2);
        rs1 += __shfl_xor_sync(0xffffffffu, rs1, 1);
        rs1 += __shfl_xor_sync(0xffffffffu, rs1, 2);
        l0 = l0 * al0 + rs0;
        l1 = l1 * al1 + rs1;
        m0 = mn0; m1 = mn1;
        #pragma unroll
        for (int nt = 0; nt < 8; nt++) {
            oacc[nt][0] *= al0; oacc[nt][1] *= al0;
            oacc[nt][2] *= al1; oacc[nt][3] *= al1;
        }

        // O += P @ V  (V s-major, b-frags via ldmatrix.trans)
        #pragma unroll
        for (int kt = 0; kt < 4; kt++) {
            unsigned pa[4];
            pa[0] = packh2(sacc[2*kt][0],     sacc[2*kt][1]);
            pa[1] = packh2(sacc[2*kt][2],     sacc[2*kt][3]);
            pa[2] = packh2(sacc[2*kt + 1][0], sacc[2*kt + 1][1]);
            pa[3] = packh2(sacc[2*kt + 1][2], sacc[2*kt + 1][3]);
            #pragma unroll
            for (int p = 0; p < 4; p++) {
                unsigned r0, r1, r2, r3;
                ldm_x4_t(r0, r1, r2, r3, vb + ((kt*16 + lmr) * 72 + p*16 + lmk) * 2);
                unsigned b0[2] = { r0, r1 }, b1[2] = { r2, r3 };
                mma16h(oacc[2*p],   pa, b0);
                mma16h(oacc[2*p+1], pa, b1);
            }
        }
    }

    float inv0 = 1.f / l0, inv1 = 1.f / l1;
    size_t r0 = ((size_t)b * Tt + t_r0) * DM + h * DH;
    size_t r1 = ((size_t)b * Tt + t_r1) * DM + h * DH;
    #pragma unroll
    for (int nt = 0; nt < 8; nt++) {
        int d = nt*8 + q*2;
        g_ctxh[r0 + d]     = __float2half_rn(oacc[nt][0] * inv0);
        g_ctxh[r0 + d + 1] = __float2half_rn(oacc[nt][1] * inv0);
        g_ctxh[r1 + d]     = __float2half_rn(oacc[nt][2] * inv1);
        g_ctxh[r1 + d + 1] = __float2half_rn(oacc[nt][3] * inv1);
    }
}

// ---------------- launch -------------------------------------------------------------------
extern "C" void kernel_launch(void* const* d_in, const int* in_sizes, int n_in,
                              void* d_out, int out_size) {
    const float* x  = (const float*)d_in[0];
    const float* wq = (const float*)d_in[1];
    const float* wk = (const float*)d_in[2];
    const float* wv = (const float*)d_in[3];
    const float* wp = (const float*)d_in[4];
    float* out = (float*)d_out;

    k_rtab   <<<(Tt * 32) / 256, 256>>>();
    k_split_x<<<(size_t)(Bb*Tt*DM) / 1024, 256>>>((const float4*)x);
    k_split_w<<<10240, 256>>>((const float4*)wq, (const float4*)wk,
                              (const float4*)wv, (const float4*)wp);

    k_gemm<0><<<dim3(DM / 128, (Bb * Tt) / 128), 256>>>(nullptr, Bb*Tt, DM, DM);
    k_gemm<1><<<dim3(1024 / 128, (Bb * SS + 127) / 128), 256>>>(nullptr, Bb*SS, 1024, DM);

    k_flash<<<dim3(Tt / 128, Bb * NH), 256>>>();

    k_gemm<2><<<dim3(DM / 128, (Bb * Tt) / 128), 256>>>(out, Bb*Tt, DM, DM);
}

// round 13
// speedup vs baseline: 15.2552x; 1.1546x over previous
#include <cuda_runtime.h>
#include <cuda_fp16.h>
#include <math.h>

#define Bb 2
#define Tt 4096
#define DM 2048
#define NH 32
#define NKV 8
#define DH 64
#define SS 1028
#define SINKN 4
#define POS_SHIFT 3068

// ---------------- scratch (16B-aligned) --------------------------------------------
__device__ __align__(16) __half g_xh  [(size_t)Bb*Tt*DM];
__device__ __align__(16) __half g_wqh [(size_t)DM*DM];
__device__ __align__(16) __half g_wkvh[(size_t)1024*DM];
__device__ __align__(16) __half g_wph [(size_t)DM*DM];
__device__ __align__(16) __half g_ctxh[(size_t)Bb*Tt*DM];
__device__ __align__(16) __half g_Qh [(size_t)Bb*NH*Tt*DH];
__device__ __align__(16) __half g_Kh [(size_t)Bb*NKV*SS*DH];
__device__ __align__(16) __half g_vtm[(size_t)Bb*SS*512];
__device__ __align__(16) float2 g_rtab[(size_t)Tt*32];

// ---------------- helpers ------------------------------------------------------------
__device__ __forceinline__ void mma16h(float c[4], const unsigned a[4], const unsigned b[2]) {
    asm volatile("mma.sync.aligned.m16n8k16.row.col.f32.f16.f16.f32 "
        "{%0,%1,%2,%3},{%4,%5,%6,%7},{%8,%9},{%0,%1,%2,%3};"
        : "+f"(c[0]), "+f"(c[1]), "+f"(c[2]), "+f"(c[3])
        : "r"(a[0]), "r"(a[1]), "r"(a[2]), "r"(a[3]), "r"(b[0]), "r"(b[1]));
}
__device__ __forceinline__ void ldm_x4(unsigned &r0, unsigned &r1, unsigned &r2, unsigned &r3,
                                       unsigned addr) {
    asm volatile("ldmatrix.sync.aligned.m8n8.x4.shared.b16 {%0,%1,%2,%3}, [%4];"
        : "=r"(r0), "=r"(r1), "=r"(r2), "=r"(r3) : "r"(addr));
}
__device__ __forceinline__ void ldm_x4_t(unsigned &r0, unsigned &r1, unsigned &r2, unsigned &r3,
                                         unsigned addr) {
    asm volatile("ldmatrix.sync.aligned.m8n8.x4.trans.shared.b16 {%0,%1,%2,%3}, [%4];"
        : "=r"(r0), "=r"(r1), "=r"(r2), "=r"(r3) : "r"(addr));
}
__device__ __forceinline__ unsigned packh2(float lo, float hi) {
    __half2 h = __floats2half2_rn(lo, hi);
    return *reinterpret_cast<unsigned*>(&h);
}
__device__ __forceinline__ unsigned smem_u32(const void* p) {
    return (unsigned)__cvta_generic_to_shared(p);
}
__device__ __forceinline__ void cpa16(unsigned dst, const void* src) {
    asm volatile("cp.async.cg.shared.global [%0], [%1], 16;" :: "r"(dst), "l"(src));
}
__device__ __forceinline__ void cpa16z(unsigned dst, const void* src, unsigned sz) {
    asm volatile("cp.async.cg.shared.global [%0], [%1], 16, %2;" :: "r"(dst), "l"(src), "r"(sz));
}
__device__ __forceinline__ uint2 pack4(float4 v) {
    __half2 h0 = __floats2half2_rn(v.x, v.y);
    __half2 h1 = __floats2half2_rn(v.z, v.w);
    return make_uint2(*reinterpret_cast<unsigned*>(&h0), *reinterpret_cast<unsigned*>(&h1));
}

// ---------------- RoPE trig table ------------------------------------------------------
__global__ void k_rtab() {
    int idx = blockIdx.x * 256 + threadIdx.x;
    int i = idx & 31, t = idx >> 5;
    double inv = pow(10000.0, -(double)i / 32.0);
    double ang = (double)t * inv;
    g_rtab[idx] = make_float2((float)cos(ang), (float)sin(ang));
}

// ---------------- split kernels ----------------------------------------------------------
__global__ void k_split_x(const float4* __restrict__ s) {
    size_t i = (size_t)blockIdx.x * blockDim.x + threadIdx.x;
    *(uint2*)&g_xh[i * 4] = pack4(s[i]);
}
__global__ void k_split_w(const float4* __restrict__ wq, const float4* __restrict__ wk,
                          const float4* __restrict__ wv, const float4* __restrict__ wp) {
    size_t i = (size_t)blockIdx.x * 256 + threadIdx.x;
    const size_t NQ = (size_t)DM * DM / 4;
    const size_t NK = (size_t)512 * DM / 4;
    if (i < NQ) {
        *(uint2*)&g_wqh[i * 4] = pack4(wq[i]);
    } else if (i < NQ + NK) {
        size_t j = i - NQ;
        *(uint2*)&g_wkvh[j * 4] = pack4(wk[j]);
    } else if (i < NQ + 2 * NK) {
        size_t j = i - NQ - NK;
        *(uint2*)&g_wkvh[(size_t)512 * DM + j * 4] = pack4(wv[j]);
    } else {
        size_t j = i - NQ - 2 * NK;
        *(uint2*)&g_wph[j * 4] = pack4(wp[j]);
    }
}

// ---------------- fp16 GEMM core, BK=32, 2-stage cp.async --------------------------------
// MODE 0: g_xh @ g_wqh^T   -> rope * 0.125 -> g_Qh      (M=8192, N=2048)
// MODE 1: gather(g_xh) @ g_wkvh^T -> rope K / V store   (M=2056, N=1024)
// MODE 2: g_ctxh @ g_wph^T -> fp32 C                    (M=8192, N=2048)
#define SK3 40   // smem row stride in halfs (32 + 8 pad)

template<int MODE>
__device__ __forceinline__ void gemm_core(int bxx, int byy, float* __restrict__ C,
                                          int M, int N, int K)
{
    const __half* A_ = (MODE == 2) ? g_ctxh : g_xh;
    const __half* W_ = (MODE == 0) ? g_wqh : (MODE == 1) ? g_wkvh : g_wph;

    __shared__ __align__(16) __half sm[2][2][128 * SK3];   // 40 KB
    int tid = threadIdx.x, lane = tid & 31, wid = tid >> 5;
    int wm = wid >> 1, wn = wid & 1, gp = lane >> 2, q = lane & 3;
    int bm = byy * 128, bn = bxx * 128;
    int lmr = lane & 15, lmk = (lane >> 4) * 8;

    float acc[2][8][4];
    #pragma unroll
    for (int mt = 0; mt < 2; mt++)
        #pragma unroll
        for (int nt = 0; nt < 8; nt++)
            #pragma unroll
            for (int i = 0; i < 4; i++) acc[mt][nt][i] = 0.f;

    // loader: each thread handles rows (tid>>2) and (tid>>2)+64, segment (tid&3)*8 halfs
    int row0 = tid >> 2, seg = (tid & 3) * 8;
    const __half* gaa[2];
    const __half* gbb[2];
    unsigned sa[2][2], sb[2][2];     // [stage][rowpair]
    #pragma unroll
    for (int j = 0; j < 2; j++) {
        int r = row0 + j * 64;
        int arow = bm + r; if (arow > M - 1) arow = M - 1;
        int brow = bn + r; if (brow > N - 1) brow = N - 1;
        if (MODE == 1) {
            int ab = arow / SS, aj = arow % SS;
            int pos = (aj < SINKN) ? aj : aj + POS_SHIFT;
            gaa[j] = A_ + ((size_t)ab * Tt + pos) * DM + seg;
        } else {
            gaa[j] = A_ + (size_t)arow * K + seg;
        }
        gbb[j] = W_ + (size_t)brow * K + seg;
        #pragma unroll
        for (int s = 0; s < 2; s++) {
            sa[s][j] = smem_u32(&sm[s][0][r * SK3 + seg]);
            sb[s][j] = smem_u32(&sm[s][1][r * SK3 + seg]);
        }
    }

    int iters = K / 32;
    // prologue: stage 0
    #pragma unroll
    for (int j = 0; j < 2; j++) { cpa16(sa[0][j], gaa[j]); cpa16(sb[0][j], gbb[j]); }
    asm volatile("cp.async.commit_group;");

    for (int i = 0; i < iters; i++) {
        asm volatile("cp.async.wait_group 0;");
        __syncthreads();
        if (i + 1 < iters) {
            int st = (i + 1) & 1, k0 = (i + 1) * 32;
            #pragma unroll
            for (int j = 0; j < 2; j++) {
                cpa16(sa[st][j], gaa[j] + k0);
                cpa16(sb[st][j], gbb[j] + k0);
            }
            asm volatile("cp.async.commit_group;");
        }

        int cur = i & 1;
        unsigned abase = smem_u32(&sm[cur][0][0]);
        unsigned bbase = smem_u32(&sm[cur][1][0]);

        unsigned a[2][2][4];   // [mt][kk]
        #pragma unroll
        for (int mt = 0; mt < 2; mt++)
            #pragma unroll
            for (int kk = 0; kk < 2; kk++)
                ldm_x4(a[mt][kk][0], a[mt][kk][1], a[mt][kk][2], a[mt][kk][3],
                       abase + ((wm*32 + mt*16 + lmr) * SK3 + kk*16 + lmk) * 2);

        #pragma unroll
        for (int p = 0; p < 4; p++) {
            #pragma unroll
            for (int kk = 0; kk < 2; kk++) {
                unsigned r0, r1, r2, r3;
                ldm_x4(r0, r1, r2, r3,
                       bbase + ((wn*64 + p*16 + lmr) * SK3 + kk*16 + lmk) * 2);
                unsigned b0[2] = { r0, r2 }, b1[2] = { r1, r3 };
                mma16h(acc[0][2*p],   a[0][kk], b0);
                mma16h(acc[1][2*p],   a[1][kk], b0);
                mma16h(acc[0][2*p+1], a[0][kk], b1);
                mma16h(acc[1][2*p+1], a[1][kk], b1);
            }
        }
    }

    // ---------------- epilogues (unchanged from round 12) ----------------
    int cb = bn + wn * 64;
    if (MODE == 0) {
        int h = cb >> 6;
        #pragma unroll
        for (int mt = 0; mt < 2; mt++) {
            int r = bm + wm * 32 + mt * 16 + gp;
            #pragma unroll
            for (int half_ = 0; half_ < 2; half_++) {
                int rr = r + half_ * 8;
                int b = rr >> 12, t = rr & 4095;
                size_t o = (((size_t)b * NH + h) * Tt + t) * DH;
                #pragma unroll
                for (int nt = 0; nt < 4; nt++) {
                    int i2 = nt * 8 + q * 2;
                    float x1a = acc[mt][nt][2*half_],     x1b = acc[mt][nt][2*half_ + 1];
                    float x2a = acc[mt][nt + 4][2*half_], x2b = acc[mt][nt + 4][2*half_ + 1];
                    float2 ca  = g_rtab[t * 32 + i2];
                    float2 cbv = g_rtab[t * 32 + i2 + 1];
                    *(unsigned*)&g_Qh[o + i2] =
                        packh2(0.125f * (x1a * ca.x - x2a * ca.y),
                               0.125f * (x1b * cbv.x - x2b * cbv.y));
                    *(unsigned*)&g_Qh[o + i2 + 32] =
                        packh2(0.125f * (x2a * ca.x + x1a * ca.y),
                               0.125f * (x2b * cbv.x + x1b * cbv.y));
                }
            }
        }
    } else if (MODE == 1) {
        int hb = cb >> 6;
        #pragma unroll
        for (int mt = 0; mt < 2; mt++) {
            int r = bm + wm * 32 + mt * 16 + gp;
            #pragma unroll
            for (int half_ = 0; half_ < 2; half_++) {
                int rr = r + half_ * 8;
                if (rr >= M) continue;
                int b = (rr >= SS) ? 1 : 0;
                int j = rr - b * SS;
                if (hb < 8) {
                    int pos = (j < SINKN) ? j : j + POS_SHIFT;
                    size_t o = (((size_t)b * NKV + hb) * SS + j) * DH;
                    #pragma unroll
                    for (int nt = 0; nt < 4; nt++) {
                        int i2 = nt * 8 + q * 2;
                        float x1a = acc[mt][nt][2*half_],     x1b = acc[mt][nt][2*half_ + 1];
                        float x2a = acc[mt][nt + 4][2*half_], x2b = acc[mt][nt + 4][2*half_ + 1];
                        float2 ca  = g_rtab[pos * 32 + i2];
                        float2 cbv = g_rtab[pos * 32 + i2 + 1];
                        *(unsigned*)&g_Kh[o + i2] =
                            packh2(x1a * ca.x - x2a * ca.y, x1b * cbv.x - x2b * cbv.y);
                        *(unsigned*)&g_Kh[o + i2 + 32] =
                            packh2(x2a * ca.x + x1a * ca.y, x2b * cbv.x + x1b * cbv.y);
                    }
                } else {
                    size_t o = ((size_t)b * SS + j) * 512 + (hb - 8) * 64;
                    #pragma unroll
                    for (int nt = 0; nt < 8; nt++) {
                        int d = nt * 8 + q * 2;
                        *(unsigned*)&g_vtm[o + d] =
                            packh2(acc[mt][nt][2*half_], acc[mt][nt][2*half_ + 1]);
                    }
                }
            }
        }
    } else {
        #pragma unroll
        for (int mt = 0; mt < 2; mt++) {
            int r = bm + wm * 32 + mt * 16 + gp;
            #pragma unroll
            for (int nt = 0; nt < 8; nt++) {
                int cc = cb + nt * 8 + q * 2;
                C[(size_t)r * N + cc]       = acc[mt][nt][0];
                C[(size_t)r * N + cc + 1]   = acc[mt][nt][1];
                C[(size_t)(r+8) * N + cc]   = acc[mt][nt][2];
                C[(size_t)(r+8) * N + cc+1] = acc[mt][nt][3];
            }
        }
    }
}

// merged Q + KV projection (1160 blocks: 1024 Q tiles + 136 KV tiles)
__global__ void __launch_bounds__(256, 2) k_gemm_qkv() {
    int bid = blockIdx.x;
    if (bid < 1024) {
        gemm_core<0>(bid & 15, bid >> 4, nullptr, Bb * Tt, DM, DM);
    } else {
        int r = bid - 1024;
        gemm_core<1>(r & 7, r >> 3, nullptr, Bb * SS, 1024, DM);
    }
}
__global__ void __launch_bounds__(256, 2) k_proj(float* __restrict__ out) {
    gemm_core<2>(blockIdx.x, blockIdx.y, out, Bb * Tt, DM, DM);
}

// ---------------- fused flash attention (unchanged from round 12) -------------------------
__global__ void __launch_bounds__(256, 2) k_flash() {
    __shared__ __align__(16) __half Ks[2][64 * 72];
    __shared__ __align__(16) __half Vs[2][64 * 72];
    int tid = threadIdx.x, lane = tid & 31, wid = tid >> 5;
    int gp = lane >> 2, q = lane & 3;
    int lmr = lane & 15, lmk = (lane >> 4) * 8;
    int t0 = blockIdx.x * 128;
    int z = blockIdx.y;
    int b = z >> 5, h = z & 31, kvh = h >> 2;
    int bk = b * NKV + kvh;
    const __half* Qp = g_Qh + (size_t)z * Tt * DH;
    const __half* Kp = g_Kh + (size_t)bk * SS * DH;
    const __half* Vp = g_vtm + (size_t)b * SS * 512 + kvh * 64;

    int t_r0 = t0 + wid * 16 + gp;
    int t_r1 = t_r0 + 8;
    int warp_tmin = t0 + wid * 16;
    int s_end = min(SS, t0 + 128);
    int ntiles = (s_end + 63) >> 6;

    unsigned kbs[2] = { smem_u32(Ks[0]), smem_u32(Ks[1]) };
    unsigned vbs[2] = { smem_u32(Vs[0]), smem_u32(Vs[1]) };

    auto load_tile = [&](int s0, int st) {
        #pragma unroll
        for (int c = 0; c < 2; c++) {
            int f = c * 256 + tid;
            int r = f >> 3, sg = (f & 7) * 8;
            int srow = s0 + r;
            unsigned sz = (srow < SS) ? 16u : 0u;
            cpa16z(kbs[st] + (r * 72 + sg) * 2, Kp + (size_t)srow * DH + sg, sz);
            cpa16z(vbs[st] + (r * 72 + sg) * 2, Vp + (size_t)srow * 512 + sg, sz);
        }
        asm volatile("cp.async.commit_group;");
    };

    unsigned qa[4][4];
    {
        const unsigned* uQ0 = (const unsigned*)(Qp + (size_t)t_r0 * DH);
        const unsigned* uQ1 = (const unsigned*)(Qp + (size_t)t_r1 * DH);
        #pragma unroll
        for (int kk = 0; kk < 4; kk++) {
            qa[kk][0] = uQ0[kk * 8 + q];
            qa[kk][1] = uQ1[kk * 8 + q];
            qa[kk][2] = uQ0[kk * 8 + q + 4];
            qa[kk][3] = uQ1[kk * 8 + q + 4];
        }
    }

    float oacc[8][4];
    #pragma unroll
    for (int nt = 0; nt < 8; nt++)
        #pragma unroll
        for (int i = 0; i < 4; i++) oacc[nt][i] = 0.f;
    float m0 = -1e30f, m1 = -1e30f, l0 = 0.f, l1 = 0.f;

    load_tile(0, 0);

    for (int ti = 0; ti < ntiles; ti++) {
        int s0 = ti * 64;
        asm volatile("cp.async.wait_group 0;");
        __syncthreads();
        if (ti + 1 < ntiles) load_tile((ti + 1) * 64, (ti + 1) & 1);

        int st = ti & 1;
        unsigned kb = kbs[st], vb = vbs[st];

        float sacc[8][4];
        #pragma unroll
        for (int nt = 0; nt < 8; nt++)
            #pragma unroll
            for (int i = 0; i < 4; i++) sacc[nt][i] = 0.f;
        #pragma unroll
        for (int kk = 0; kk < 4; kk++) {
            #pragma unroll
            for (int p = 0; p < 4; p++) {
                unsigned r0, r1, r2, r3;
                ldm_x4(r0, r1, r2, r3, kb + ((p*16 + lmr) * 72 + kk*16 + lmk) * 2);
                unsigned b0[2] = { r0, r2 }, b1[2] = { r1, r3 };
                mma16h(sacc[2*p],   qa[kk], b0);
                mma16h(sacc[2*p+1], qa[kk], b1);
            }
        }

        bool nomask = (s0 + 63 <= warp_tmin) && (s0 + 64 <= SS);
        if (!nomask) {
            #pragma unroll
            for (int nt = 0; nt < 8; nt++) {
                int j = s0 + nt*8 + q*2;
                if (!(j     <= t_r0 && j     < SS)) sacc[nt][0] = -1e30f;
                if (!(j + 1 <= t_r0 && j + 1 < SS)) sacc[nt][1] = -1e30f;
                if (!(j     <= t_r1 && j     < SS)) sacc[nt][2] = -1e30f;
                if (!(j + 1 <= t_r1 && j + 1 < SS)) sacc[nt][3] = -1e30f;
            }
        }

        float mx0 = -1e30f, mx1 = -1e30f;
        #pragma unroll
        for (int nt = 0; nt < 8; nt++) {
            mx0 = fmaxf(mx0, fmaxf(sacc[nt][0], sacc[nt][1]));
            mx1 = fmaxf(mx1, fmaxf(sacc[nt][2], sacc[nt][3]));
        }
        mx0 = fmaxf(mx0, __shfl_xor_sync(0xffffffffu, mx0, 1));
        mx0 = fmaxf(mx0, __shfl_xor_sync(0xffffffffu, mx0, 2));
        mx1 = fmaxf(mx1, __shfl_xor_sync(0xffffffffu, mx1, 1));
        mx1 = fmaxf(mx1, __shfl_xor_sync(0xffffffffu, mx1, 2));
        float mn0 = fmaxf(m0, mx0), mn1 = fmaxf(m1, mx1);
        float al0 = __expf(m0 - mn0), al1 = __expf(m1 - mn1);
        float rs0 = 0.f, rs1 = 0.f;
        #pragma unroll
        for (int nt = 0; nt < 8; nt++) {
            float p0 = __expf(sacc[nt][0] - mn0); sacc[nt][0] = p0; rs0 += p0;
            float p1 = __expf(sacc[nt][1] - mn0); sacc[nt][1] = p1; rs0 += p1;
            float p2 = __expf(sacc[nt][2] - mn1); sacc[nt][2] = p2; rs1 += p2;
            float p3 = __expf(sacc[nt][3] - mn1); sacc[nt][3] = p3; rs1 += p3;
        }
        rs0 += __shfl_xor_sync(0xffffffffu, rs0, 1);
        rs0 += __shfl_xor_sync(0xffffffffu, rs0, 2);
        rs1 += __shfl_xor_sync(0xffffffffu, rs1, 1);
        rs1 += __shfl_xor_sync(0xffffffffu, rs1, 2);
        l0 = l0 * al0 + rs0;
        l1 = l1 * al1 + rs1;
        m0 = mn0; m1 = mn1;
        #pragma unroll
        for (int nt = 0; nt < 8; nt++) {
            oacc[nt][0] *= al0; oacc[nt][1] *= al0;
            oacc[nt][2] *= al1; oacc[nt][3] *= al1;
        }

        #pragma unroll
        for (int kt = 0; kt < 4; kt++) {
            unsigned pa[4];
            pa[0] = packh2(sacc[2*kt][0],     sacc[2*kt][1]);
            pa[1] = packh2(sacc[2*kt][2],     sacc[2*kt][3]);
            pa[2] = packh2(sacc[2*kt + 1][0], sacc[2*kt + 1][1]);
            pa[3] = packh2(sacc[2*kt + 1][2], sacc[2*kt + 1][3]);
            #pragma unroll
            for (int p = 0; p < 4; p++) {
                unsigned r0, r1, r2, r3;
                ldm_x4_t(r0, r1, r2, r3, vb + ((kt*16 + lmr) * 72 + p*16 + lmk) * 2);
                unsigned b0[2] = { r0, r1 }, b1[2] = { r2, r3 };
                mma16h(oacc[2*p],   pa, b0);
                mma16h(oacc[2*p+1], pa, b1);
            }
        }
    }

    float inv0 = 1.f / l0, inv1 = 1.f / l1;
    size_t r0 = ((size_t)b * Tt + t_r0) * DM + h * DH;
    size_t r1 = ((size_t)b * Tt + t_r1) * DM + h * DH;
    #pragma unroll
    for (int nt = 0; nt < 8; nt++) {
        int d = nt*8 + q*2;
        g_ctxh[r0 + d]     = __float2half_rn(oacc[nt][0] * inv0);
        g_ctxh[r0 + d + 1] = __float2half_rn(oacc[nt][1] * inv0);
        g_ctxh[r1 + d]     = __float2half_rn(oacc[nt][2] * inv1);
        g_ctxh[r1 + d + 1] = __float2half_rn(oacc[nt][3] * inv1);
    }
}

// ---------------- launch -------------------------------------------------------------------
extern "C" void kernel_launch(void* const* d_in, const int* in_sizes, int n_in,
                              void* d_out, int out_size) {
    const float* x  = (const float*)d_in[0];
    const float* wq = (const float*)d_in[1];
    const float* wk = (const float*)d_in[2];
    const float* wv = (const float*)d_in[3];
    const float* wp = (const float*)d_in[4];
    float* out = (float*)d_out;

    k_rtab   <<<(Tt * 32) / 256, 256>>>();
    k_split_x<<<(size_t)(Bb*Tt*DM) / 1024, 256>>>((const float4*)x);
    k_split_w<<<10240, 256>>>((const float4*)wq, (const float4*)wk,
                              (const float4*)wv, (const float4*)wp);

    k_gemm_qkv<<<1024 + 136, 256>>>();

    k_flash<<<dim3(Tt / 128, Bb * NH), 256>>>();

    k_proj<<<dim3(DM / 128, (Bb * Tt) / 128), 256>>>(out);
}